// round 2
// baseline (speedup 1.0000x reference)
#include <cuda_runtime.h>
#include <math.h>

// Problem constants
#define Sq   2048
#define Dm   512
#define NH   8
#define DKh  64
#define NB   2
#define FFd  2048
#define MROWS (NB*Sq)   // 4096

// ---------------- scratch (static device globals; no allocs) ----------------
__device__ float g_q  [MROWS*Dm];
__device__ float g_k  [MROWS*Dm];
__device__ float g_v  [MROWS*Dm];
__device__ float g_t0 [MROWS*Dm];
__device__ float g_o1 [MROWS*Dm];
__device__ float g_o2 [MROWS*Dm];
__device__ float g_ffh[MROWS*FFd];

// ---------------- generic NN GEMM: C = A[M,K] @ B[K,N] (+bias)(+relu) ------
// BM=128, BN=128, BK=8, TM=8, TN=8, 256 threads
template<bool RELU, bool BIAS>
__global__ void __launch_bounds__(256) gemm_nn(
    const float* __restrict__ A, const float* __restrict__ B,
    const float* __restrict__ bias, float* __restrict__ C,
    int M, int N, int K)
{
    __shared__ float As[8][129];
    __shared__ float Bs[8][128];

    const int t  = threadIdx.x;
    const int m0 = blockIdx.y * 128;
    const int n0 = blockIdx.x * 128;
    const int ty = t >> 4;       // 0..15
    const int tx = t & 15;       // 0..15

    float acc[8][8];
#pragma unroll
    for (int i = 0; i < 8; i++)
#pragma unroll
        for (int j = 0; j < 8; j++) acc[i][j] = 0.f;

    for (int k0 = 0; k0 < K; k0 += 8) {
        // load A tile 128x8, store transposed As[k][m]
        {
            int row = t >> 1, c4 = t & 1;
            float4 va = *(const float4*)&A[(size_t)(m0 + row) * K + k0 + c4 * 4];
            As[c4*4+0][row] = va.x; As[c4*4+1][row] = va.y;
            As[c4*4+2][row] = va.z; As[c4*4+3][row] = va.w;
        }
        // load B tile 8x128 direct Bs[k][n]
        {
            int row = t >> 5, c4 = t & 31;
            *(float4*)&Bs[row][c4*4] =
                *(const float4*)&B[(size_t)(k0 + row) * N + n0 + c4 * 4];
        }
        __syncthreads();
#pragma unroll
        for (int k = 0; k < 8; k++) {
            float ra[8], rb[8];
#pragma unroll
            for (int i = 0; i < 8; i++) ra[i] = As[k][ty*8 + i];
            float4 b0 = *(const float4*)&Bs[k][tx*8];
            float4 b1 = *(const float4*)&Bs[k][tx*8 + 4];
            rb[0]=b0.x; rb[1]=b0.y; rb[2]=b0.z; rb[3]=b0.w;
            rb[4]=b1.x; rb[5]=b1.y; rb[6]=b1.z; rb[7]=b1.w;
#pragma unroll
            for (int i = 0; i < 8; i++)
#pragma unroll
                for (int j = 0; j < 8; j++)
                    acc[i][j] = fmaf(ra[i], rb[j], acc[i][j]);
        }
        __syncthreads();
    }

#pragma unroll
    for (int i = 0; i < 8; i++) {
        size_t ro = (size_t)(m0 + ty*8 + i) * N + n0 + tx*8;
#pragma unroll
        for (int j = 0; j < 8; j += 4) {
            float4 v;
            v.x = acc[i][j+0]; v.y = acc[i][j+1];
            v.z = acc[i][j+2]; v.w = acc[i][j+3];
            if (BIAS) {
                const float4 vb = *(const float4*)&bias[n0 + tx*8 + j];
                v.x += vb.x; v.y += vb.y; v.z += vb.z; v.w += vb.w;
            }
            if (RELU) {
                v.x = fmaxf(v.x, 0.f); v.y = fmaxf(v.y, 0.f);
                v.z = fmaxf(v.z, 0.f); v.w = fmaxf(v.w, 0.f);
            }
            *(float4*)&C[ro + j] = v;
        }
    }
}

// ---------------- attention logits: out[bh,i,j] = scale*Q_i.K_j (+causal) ---
// BM=BN=128, K=64 (head dim), 256 threads, 8x8 per thread
__global__ void __launch_bounds__(256) attn_logits(
    const float* __restrict__ Q, const float* __restrict__ Km,
    float* __restrict__ out, int causal)
{
    const int bh = blockIdx.z;
    const int b  = bh >> 3, h = bh & 7;
    const int i0 = blockIdx.y * 128;
    const int j0 = blockIdx.x * 128;
    const int t  = threadIdx.x;
    float* Ob = out + (size_t)bh * Sq * Sq;

    if (causal && j0 > i0 + 127) {
        // fully masked tile: skip dot product entirely
        for (int idx = t; idx < 128*128; idx += 256) {
            int ii = idx >> 7, jj = idx & 127;
            Ob[(size_t)(i0 + ii) * Sq + j0 + jj] = -1e9f;
        }
        return;
    }

    const float* Qb = Q  + (size_t)b * Sq * Dm + h * DKh;
    const float* Kb = Km + (size_t)b * Sq * Dm + h * DKh;

    __shared__ float Qs[8][129];
    __shared__ float Ks[8][129];

    const int ty = t >> 4;
    const int tx = t & 15;
    float acc[8][8];
#pragma unroll
    for (int i = 0; i < 8; i++)
#pragma unroll
        for (int j = 0; j < 8; j++) acc[i][j] = 0.f;

    for (int k0 = 0; k0 < DKh; k0 += 8) {
        {
            int row = t >> 1, c4 = t & 1;
            float4 v = *(const float4*)&Qb[(size_t)(i0 + row) * Dm + k0 + c4*4];
            Qs[c4*4+0][row] = v.x; Qs[c4*4+1][row] = v.y;
            Qs[c4*4+2][row] = v.z; Qs[c4*4+3][row] = v.w;
        }
        {
            int row = t >> 1, c4 = t & 1;
            float4 v = *(const float4*)&Kb[(size_t)(j0 + row) * Dm + k0 + c4*4];
            Ks[c4*4+0][row] = v.x; Ks[c4*4+1][row] = v.y;
            Ks[c4*4+2][row] = v.z; Ks[c4*4+3][row] = v.w;
        }
        __syncthreads();
#pragma unroll
        for (int k = 0; k < 8; k++) {
            float ra[8], rb[8];
#pragma unroll
            for (int i = 0; i < 8; i++) ra[i] = Qs[k][ty*8 + i];
#pragma unroll
            for (int j = 0; j < 8; j++) rb[j] = Ks[k][tx*8 + j];
#pragma unroll
            for (int i = 0; i < 8; i++)
#pragma unroll
                for (int j = 0; j < 8; j++)
                    acc[i][j] = fmaf(ra[i], rb[j], acc[i][j]);
        }
        __syncthreads();
    }

    const float scale = 0.125f;  // 1/sqrt(64)
#pragma unroll
    for (int i = 0; i < 8; i++) {
        const int gi = i0 + ty*8 + i;
        size_t ro = (size_t)gi * Sq + j0 + tx*8;
#pragma unroll
        for (int j = 0; j < 8; j += 4) {
            float4 v;
            int gj = j0 + tx*8 + j;
            v.x = acc[i][j+0] * scale + ((causal && gj+0 > gi) ? -1e9f : 0.f);
            v.y = acc[i][j+1] * scale + ((causal && gj+1 > gi) ? -1e9f : 0.f);
            v.z = acc[i][j+2] * scale + ((causal && gj+2 > gi) ? -1e9f : 0.f);
            v.w = acc[i][j+3] * scale + ((causal && gj+3 > gi) ? -1e9f : 0.f);
            *(float4*)&Ob[ro + j] = v;
        }
    }
}

// ---------------- row softmax in-place, row length 2048 ---------------------
__global__ void __launch_bounds__(256) softmax_rows(float* __restrict__ aw)
{
    const size_t row = blockIdx.x;
    float* p = aw + row * Sq;
    const int t = threadIdx.x;
    __shared__ float red[8];

    float v[8];
#pragma unroll
    for (int i = 0; i < 8; i++) v[i] = p[t + i*256];

    float mx = v[0];
#pragma unroll
    for (int i = 1; i < 8; i++) mx = fmaxf(mx, v[i]);
#pragma unroll
    for (int o = 16; o; o >>= 1) mx = fmaxf(mx, __shfl_xor_sync(0xffffffffu, mx, o));
    if ((t & 31) == 0) red[t >> 5] = mx;
    __syncthreads();
    mx = red[0];
#pragma unroll
    for (int w = 1; w < 8; w++) mx = fmaxf(mx, red[w]);

    float sum = 0.f;
#pragma unroll
    for (int i = 0; i < 8; i++) { v[i] = __expf(v[i] - mx); sum += v[i]; }
#pragma unroll
    for (int o = 16; o; o >>= 1) sum += __shfl_xor_sync(0xffffffffu, sum, o);
    __syncthreads();
    if ((t & 31) == 0) red[t >> 5] = sum;
    __syncthreads();
    sum = red[0];
#pragma unroll
    for (int w = 1; w < 8; w++) sum += red[w];

    const float inv = 1.f / sum;
#pragma unroll
    for (int i = 0; i < 8; i++) p[t + i*256] = v[i] * inv;
}

// ---------------- AV: out[b,i,h*64+d] = sum_j aw[bh,i,j] * V[b,j,h*64+d] ----
// BM=128, BN=64, BK=8, TM=8, TN=4, 256 threads
__global__ void __launch_bounds__(256) attn_av(
    const float* __restrict__ aw, const float* __restrict__ V,
    float* __restrict__ out)
{
    const int bh = blockIdx.z;
    const int b  = bh >> 3, h = bh & 7;
    const int i0 = blockIdx.y * 128;
    const int t  = threadIdx.x;

    const float* Ab = aw  + (size_t)bh * Sq * Sq;
    const float* Bb = V   + (size_t)b * Sq * Dm + h * DKh;
    float*       Cb = out + (size_t)b * Sq * Dm + h * DKh;

    __shared__ float As[8][129];
    __shared__ float Bs[8][64];

    const int ty = t >> 4;
    const int tx = t & 15;
    float acc[8][4];
#pragma unroll
    for (int i = 0; i < 8; i++)
#pragma unroll
        for (int j = 0; j < 4; j++) acc[i][j] = 0.f;

    for (int k0 = 0; k0 < Sq; k0 += 8) {
        {
            int row = t >> 1, c4 = t & 1;
            float4 v = *(const float4*)&Ab[(size_t)(i0 + row) * Sq + k0 + c4*4];
            As[c4*4+0][row] = v.x; As[c4*4+1][row] = v.y;
            As[c4*4+2][row] = v.z; As[c4*4+3][row] = v.w;
        }
        if (t < 128) {
            int row = t >> 4, c4 = t & 15;
            *(float4*)&Bs[row][c4*4] =
                *(const float4*)&Bb[(size_t)(k0 + row) * Dm + c4*4];
        }
        __syncthreads();
#pragma unroll
        for (int k = 0; k < 8; k++) {
            float ra[8];
#pragma unroll
            for (int i = 0; i < 8; i++) ra[i] = As[k][ty*8 + i];
            float4 b0 = *(const float4*)&Bs[k][tx*4];
            float rb[4] = {b0.x, b0.y, b0.z, b0.w};
#pragma unroll
            for (int i = 0; i < 8; i++)
#pragma unroll
                for (int j = 0; j < 4; j++)
                    acc[i][j] = fmaf(ra[i], rb[j], acc[i][j]);
        }
        __syncthreads();
    }

#pragma unroll
    for (int i = 0; i < 8; i++) {
        float4 v; v.x = acc[i][0]; v.y = acc[i][1]; v.z = acc[i][2]; v.w = acc[i][3];
        *(float4*)&Cb[(size_t)(i0 + ty*8 + i) * Dm + tx*4] = v;
    }
}

// ---------------- residual add + layernorm over last dim (512) --------------
__global__ void __launch_bounds__(128) add_ln(
    const float* __restrict__ a, const float* __restrict__ r,
    const float* __restrict__ g, const float* __restrict__ be,
    float* __restrict__ out)
{
    const size_t row = blockIdx.x;
    const int t = threadIdx.x;  // 128 threads, 4 floats each
    __shared__ float red[4];

    float4 va = *(const float4*)&a[row * Dm + t*4];
    float4 vr = *(const float4*)&r[row * Dm + t*4];
    float x0 = va.x + vr.x, x1 = va.y + vr.y, x2 = va.z + vr.z, x3 = va.w + vr.w;

    float s = x0 + x1 + x2 + x3;
#pragma unroll
    for (int o = 16; o; o >>= 1) s += __shfl_xor_sync(0xffffffffu, s, o);
    if ((t & 31) == 0) red[t >> 5] = s;
    __syncthreads();
    float mean = (red[0] + red[1] + red[2] + red[3]) * (1.f / 512.f);

    float d0 = x0 - mean, d1 = x1 - mean, d2 = x2 - mean, d3 = x3 - mean;
    float vs = d0*d0 + d1*d1 + d2*d2 + d3*d3;
#pragma unroll
    for (int o = 16; o; o >>= 1) vs += __shfl_xor_sync(0xffffffffu, vs, o);
    __syncthreads();
    if ((t & 31) == 0) red[t >> 5] = vs;
    __syncthreads();
    float var = (red[0] + red[1] + red[2] + red[3]) * (1.f / 512.f);
    float rstd = rsqrtf(var + 1e-6f);

    float4 vg = *(const float4*)&g[t*4];
    float4 vb = *(const float4*)&be[t*4];
    float4 o4;
    o4.x = d0 * rstd * vg.x + vb.x;
    o4.y = d1 * rstd * vg.y + vb.y;
    o4.z = d2 * rstd * vg.z + vb.z;
    o4.w = d3 * rstd * vg.w + vb.w;
    *(float4*)&out[row * Dm + t*4] = o4;
}

// ---------------- launch ----------------------------------------------------
extern "C" void kernel_launch(void* const* d_in, const int* in_sizes, int n_in,
                              void* d_out, int out_size)
{
    const float* x    = (const float*)d_in[0];
    const float* enc  = (const float*)d_in[1];
    // d_in[2] = look_ahead_mask (causality applied analytically)
    const float* wq1 = (const float*)d_in[3],  *bq1 = (const float*)d_in[4];
    const float* wk1 = (const float*)d_in[5],  *bk1 = (const float*)d_in[6];
    const float* wv1 = (const float*)d_in[7],  *bv1 = (const float*)d_in[8];
    const float* wo1 = (const float*)d_in[9],  *bo1 = (const float*)d_in[10];
    const float* wq2 = (const float*)d_in[11], *bq2 = (const float*)d_in[12];
    const float* wk2 = (const float*)d_in[13], *bk2 = (const float*)d_in[14];
    const float* wv2 = (const float*)d_in[15], *bv2 = (const float*)d_in[16];
    const float* wo2 = (const float*)d_in[17], *bo2 = (const float*)d_in[18];
    const float* wf1 = (const float*)d_in[19], *bf1 = (const float*)d_in[20];
    const float* wf2 = (const float*)d_in[21], *bf2 = (const float*)d_in[22];
    const float* g1 = (const float*)d_in[23], *be1 = (const float*)d_in[24];
    const float* g2 = (const float*)d_in[25], *be2 = (const float*)d_in[26];
    const float* g3 = (const float*)d_in[27], *be3 = (const float*)d_in[28];

    float* out3 = (float*)d_out;
    float* aw1  = out3 + (size_t)NB * Sq * Dm;                  // + 2,097,152
    float* aw2  = aw1  + (size_t)NB * NH * Sq * Sq;             // + 67,108,864

    float *q, *k, *v, *t0, *o1, *o2, *ffh;
    cudaGetSymbolAddress((void**)&q,   g_q);
    cudaGetSymbolAddress((void**)&k,   g_k);
    cudaGetSymbolAddress((void**)&v,   g_v);
    cudaGetSymbolAddress((void**)&t0,  g_t0);
    cudaGetSymbolAddress((void**)&o1,  g_o1);
    cudaGetSymbolAddress((void**)&o2,  g_o2);
    cudaGetSymbolAddress((void**)&ffh, g_ffh);

    const dim3 gProj(Dm / 128, MROWS / 128);        // (4, 32)
    const dim3 gFF1(FFd / 128, MROWS / 128);        // (16, 32)
    const dim3 gLog(Sq / 128, Sq / 128, NB * NH);   // (16, 16, 16)
    const dim3 gAV(1, Sq / 128, NB * NH);           // (1, 16, 16)

    // ---- self attention ----
    gemm_nn<false, true><<<gProj, 256>>>(x, wq1, bq1, q, MROWS, Dm, Dm);
    gemm_nn<false, true><<<gProj, 256>>>(x, wk1, bk1, k, MROWS, Dm, Dm);
    gemm_nn<false, true><<<gProj, 256>>>(x, wv1, bv1, v, MROWS, Dm, Dm);
    attn_logits<<<gLog, 256>>>(q, k, aw1, 1);
    softmax_rows<<<NB * NH * Sq, 256>>>(aw1);
    attn_av<<<gAV, 256>>>(aw1, v, t0);
    gemm_nn<false, true><<<gProj, 256>>>(t0, wo1, bo1, q, MROWS, Dm, Dm);
    add_ln<<<MROWS, 128>>>(q, x, g1, be1, o1);

    // ---- cross attention ----
    gemm_nn<false, true><<<gProj, 256>>>(o1, wq2, bq2, q, MROWS, Dm, Dm);
    gemm_nn<false, true><<<gProj, 256>>>(enc, wk2, bk2, k, MROWS, Dm, Dm);
    gemm_nn<false, true><<<gProj, 256>>>(enc, wv2, bv2, v, MROWS, Dm, Dm);
    attn_logits<<<gLog, 256>>>(q, k, aw2, 0);
    softmax_rows<<<NB * NH * Sq, 256>>>(aw2);
    attn_av<<<gAV, 256>>>(aw2, v, t0);
    gemm_nn<false, true><<<gProj, 256>>>(t0, wo2, bo2, q, MROWS, Dm, Dm);
    add_ln<<<MROWS, 128>>>(q, o1, g2, be2, o2);

    // ---- FFN ----
    gemm_nn<true,  true><<<gFF1, 256>>>(o2, wf1, bf1, ffh, MROWS, FFd, Dm);
    gemm_nn<false, true><<<gProj, 256>>>(ffh, wf2, bf2, t0, MROWS, Dm, FFd);
    add_ln<<<MROWS, 128>>>(t0, o2, g3, be3, out3);
}

// round 4
// speedup vs baseline: 1.4307x; 1.4307x over previous
#include <cuda_runtime.h>
#include <math.h>
#include <stdint.h>
#include <mma.h>

using namespace nvcuda;

// Problem constants
#define Sq   2048
#define Dm   512
#define NH   8
#define DKh  64
#define NB   2
#define FFd  2048
#define MROWS (NB*Sq)   // 4096

// ---------------- scratch (static device globals; no allocs) ----------------
__device__ float g_q  [MROWS*Dm];
__device__ float g_k  [MROWS*Dm];
__device__ float g_v  [MROWS*Dm];
__device__ float g_t0 [MROWS*Dm];
__device__ float g_o1 [MROWS*Dm];
__device__ float g_o2 [MROWS*Dm];
__device__ float g_ffh[MROWS*FFd];

#define TF32(x) wmma::__float_to_tf32(x)

// ================= WMMA tf32 GEMM: C = A[M,K] @ B[K,N] + bias ===============
// BM=128, BN=128, BK=16, 256 threads (8 warps: 4 along M x 2 along N)
template<bool RELU>
__global__ void __launch_bounds__(256) wm_gemm(
    const float* __restrict__ A, const float* __restrict__ B,
    const float* __restrict__ bias, float* __restrict__ C,
    int M, int N, int K)
{
    __shared__ float As[128][24];    // stride 24 floats = 96B (32B aligned rows)
    __shared__ float Bs[16][136];    // stride 136 floats = 544B
    __shared__ float BiasS[16][136];

    const int t = threadIdx.x;
    const int wid = t >> 5;
    const int m0 = blockIdx.y * 128, n0 = blockIdx.x * 128;
    const int wm = (wid & 3) * 32;   // warp row offset
    const int wn = (wid >> 2) * 64;  // warp col offset

    // replicate bias slice across 16 rows (so acc frags can be bias-initialized)
    {
        int col = t & 127, r0 = (t >> 7) * 8;
        float bv = bias[n0 + col];
#pragma unroll
        for (int r = 0; r < 8; r++) BiasS[r0 + r][col] = bv;
    }
    __syncthreads();

    wmma::fragment<wmma::accumulator, 16, 16, 8, float> acc[2][4];
#pragma unroll
    for (int i = 0; i < 2; i++)
#pragma unroll
        for (int j = 0; j < 4; j++)
            wmma::load_matrix_sync(acc[i][j], &BiasS[0][wn + j*16], 136,
                                   wmma::mem_row_major);
    __syncthreads();

    for (int k0 = 0; k0 < K; k0 += 16) {
        // A tile 128x16: 2 threads per row, 8 floats each
        {
            int row = t >> 1, cb = (t & 1) * 8;
            const float* s = A + (size_t)(m0 + row) * K + k0 + cb;
            float4 v0 = *(const float4*)s;
            float4 v1 = *(const float4*)(s + 4);
            As[row][cb+0] = TF32(v0.x); As[row][cb+1] = TF32(v0.y);
            As[row][cb+2] = TF32(v0.z); As[row][cb+3] = TF32(v0.w);
            As[row][cb+4] = TF32(v1.x); As[row][cb+5] = TF32(v1.y);
            As[row][cb+6] = TF32(v1.z); As[row][cb+7] = TF32(v1.w);
        }
        // B tile 16x128: 16 threads per row, 8 floats each
        {
            int row = t >> 4, cb = (t & 15) * 8;
            const float* s = B + (size_t)(k0 + row) * N + n0 + cb;
            float4 v0 = *(const float4*)s;
            float4 v1 = *(const float4*)(s + 4);
            Bs[row][cb+0] = TF32(v0.x); Bs[row][cb+1] = TF32(v0.y);
            Bs[row][cb+2] = TF32(v0.z); Bs[row][cb+3] = TF32(v0.w);
            Bs[row][cb+4] = TF32(v1.x); Bs[row][cb+5] = TF32(v1.y);
            Bs[row][cb+6] = TF32(v1.z); Bs[row][cb+7] = TF32(v1.w);
        }
        __syncthreads();
#pragma unroll
        for (int ks = 0; ks < 16; ks += 8) {
            wmma::fragment<wmma::matrix_a, 16, 16, 8, wmma::precision::tf32,
                           wmma::row_major> af[2];
            wmma::fragment<wmma::matrix_b, 16, 16, 8, wmma::precision::tf32,
                           wmma::row_major> bf[4];
#pragma unroll
            for (int i = 0; i < 2; i++)
                wmma::load_matrix_sync(af[i], &As[wm + i*16][ks], 24);
#pragma unroll
            for (int j = 0; j < 4; j++)
                wmma::load_matrix_sync(bf[j], &Bs[ks][wn + j*16], 136);
#pragma unroll
            for (int i = 0; i < 2; i++)
#pragma unroll
                for (int j = 0; j < 4; j++)
                    wmma::mma_sync(acc[i][j], af[i], bf[j], acc[i][j]);
        }
        __syncthreads();
    }

#pragma unroll
    for (int i = 0; i < 2; i++)
#pragma unroll
        for (int j = 0; j < 4; j++) {
            if (RELU) {
#pragma unroll
                for (int e = 0; e < acc[i][j].num_elements; e++)
                    acc[i][j].x[e] = fmaxf(acc[i][j].x[e], 0.f);
            }
            wmma::store_matrix_sync(
                &C[(size_t)(m0 + wm + i*16) * N + n0 + wn + j*16],
                acc[i][j], N, wmma::mem_row_major);
        }
}

// ============ WMMA tf32 logits: scale * Q @ K^T (+causal mask) ==============
// BM=BN=128, K=64 in one shot, 256 threads
__global__ void __launch_bounds__(256) wm_logits(
    const float* __restrict__ Q, const float* __restrict__ Km,
    float* __restrict__ out, int causal)
{
    extern __shared__ __align__(128) char smem[];
    float (*Qs)[72] = (float(*)[72])smem;                 // 128x72 = 36864B
    float (*Ks)[72] = (float(*)[72])(smem + 36864);       // 128x72
    float (*St)[136] = (float(*)[136])smem;               // stage 128x136 = 69632B

    const int bh = blockIdx.z;
    const int b = bh >> 3, h = bh & 7;
    const int i0 = blockIdx.y * 128, j0 = blockIdx.x * 128;
    const int t = threadIdx.x;
    const int wid = t >> 5;
    float* Ob = out + (size_t)bh * Sq * Sq;

    if (causal && j0 > i0 + 127) {
        for (int idx = t; idx < 128 * 128; idx += 256) {
            int ii = idx >> 7, jj = idx & 127;
            Ob[(size_t)(i0 + ii) * Sq + j0 + jj] = -1e9f;
        }
        return;
    }

    const float* Qb = Q  + (size_t)b * Sq * Dm + h * DKh;
    const float* Kb = Km + (size_t)b * Sq * Dm + h * DKh;

    // load Q,K tiles 128x64 (2 threads/row, 32 floats each)
    {
        int row = t >> 1, cb = (t & 1) * 32;
        const float* sq = Qb + (size_t)(i0 + row) * Dm + cb;
        const float* sk = Kb + (size_t)(j0 + row) * Dm + cb;
#pragma unroll
        for (int u = 0; u < 8; u++) {
            float4 v = *(const float4*)(sq + u * 4);
            Qs[row][cb + u*4 + 0] = TF32(v.x); Qs[row][cb + u*4 + 1] = TF32(v.y);
            Qs[row][cb + u*4 + 2] = TF32(v.z); Qs[row][cb + u*4 + 3] = TF32(v.w);
        }
#pragma unroll
        for (int u = 0; u < 8; u++) {
            float4 v = *(const float4*)(sk + u * 4);
            Ks[row][cb + u*4 + 0] = TF32(v.x); Ks[row][cb + u*4 + 1] = TF32(v.y);
            Ks[row][cb + u*4 + 2] = TF32(v.z); Ks[row][cb + u*4 + 3] = TF32(v.w);
        }
    }
    __syncthreads();

    const int wm = (wid & 3) * 32, wn = (wid >> 2) * 64;
    wmma::fragment<wmma::accumulator, 16, 16, 8, float> acc[2][4];
#pragma unroll
    for (int i = 0; i < 2; i++)
#pragma unroll
        for (int j = 0; j < 4; j++) wmma::fill_fragment(acc[i][j], 0.f);

#pragma unroll
    for (int ks = 0; ks < 64; ks += 8) {
        wmma::fragment<wmma::matrix_a, 16, 16, 8, wmma::precision::tf32,
                       wmma::row_major> af[2];
        wmma::fragment<wmma::matrix_b, 16, 16, 8, wmma::precision::tf32,
                       wmma::col_major> bf[4];
#pragma unroll
        for (int i = 0; i < 2; i++)
            wmma::load_matrix_sync(af[i], &Qs[wm + i*16][ks], 72);
#pragma unroll
        for (int j = 0; j < 4; j++)
            wmma::load_matrix_sync(bf[j], &Ks[wn + j*16][ks], 72);
#pragma unroll
        for (int i = 0; i < 2; i++)
#pragma unroll
            for (int j = 0; j < 4; j++)
                wmma::mma_sync(acc[i][j], af[i], bf[j], acc[i][j]);
    }
    __syncthreads();   // done with Qs/Ks; reuse as staging

#pragma unroll
    for (int i = 0; i < 2; i++)
#pragma unroll
        for (int j = 0; j < 4; j++)
            wmma::store_matrix_sync(&St[wm + i*16][wn + j*16], acc[i][j], 136,
                                    wmma::mem_row_major);
    __syncthreads();

    // epilogue: scale + causal, coalesced global write
    {
        int row = t >> 1, cb = (t & 1) * 64;
        int gi = i0 + row;
        float* orow = Ob + (size_t)gi * Sq + j0 + cb;
#pragma unroll
        for (int u = 0; u < 16; u++) {
            float4 v;
            int gj = j0 + cb + u * 4;
            v.x = St[row][cb + u*4 + 0] * 0.125f + ((causal && gj+0 > gi) ? -1e9f : 0.f);
            v.y = St[row][cb + u*4 + 1] * 0.125f + ((causal && gj+1 > gi) ? -1e9f : 0.f);
            v.z = St[row][cb + u*4 + 2] * 0.125f + ((causal && gj+2 > gi) ? -1e9f : 0.f);
            v.w = St[row][cb + u*4 + 3] * 0.125f + ((causal && gj+3 > gi) ? -1e9f : 0.f);
            *(float4*)(orow + u * 4) = v;
        }
    }
}

// ============ WMMA tf32 AV: out[b,i,h*64+d] = sum_j aw[bh,i,j] V[b,j,h*64+d]
// BM=128, BN=64, BK=16, 256 threads (8 warps: 4 along M x 2 along N)
__global__ void __launch_bounds__(256) wm_av(
    const float* __restrict__ aw, const float* __restrict__ V,
    float* __restrict__ out)
{
    __shared__ float As[128][24];
    __shared__ float Bs[16][72];

    const int bh = blockIdx.y;
    const int b = bh >> 3, h = bh & 7;
    const int i0 = blockIdx.x * 128;
    const int t = threadIdx.x;
    const int wid = t >> 5;

    const float* Abase = aw + (size_t)bh * Sq * Sq + (size_t)i0 * Sq;
    const float* Bbase = V + (size_t)b * Sq * Dm + h * DKh;
    float*       Cb    = out + (size_t)b * Sq * Dm + h * DKh;

    const int wm = (wid & 3) * 32, wn = (wid >> 2) * 32;
    wmma::fragment<wmma::accumulator, 16, 16, 8, float> acc[2][2];
#pragma unroll
    for (int i = 0; i < 2; i++)
#pragma unroll
        for (int j = 0; j < 2; j++) wmma::fill_fragment(acc[i][j], 0.f);

    for (int k0 = 0; k0 < Sq; k0 += 16) {
        // A tile 128x16
        {
            int row = t >> 1, cb = (t & 1) * 8;
            const float* s = Abase + (size_t)row * Sq + k0 + cb;
            float4 v0 = *(const float4*)s;
            float4 v1 = *(const float4*)(s + 4);
            As[row][cb+0] = TF32(v0.x); As[row][cb+1] = TF32(v0.y);
            As[row][cb+2] = TF32(v0.z); As[row][cb+3] = TF32(v0.w);
            As[row][cb+4] = TF32(v1.x); As[row][cb+5] = TF32(v1.y);
            As[row][cb+6] = TF32(v1.z); As[row][cb+7] = TF32(v1.w);
        }
        // B tile 16x64 (V rows): 16 threads/row? -> 256 threads, 4 floats each
        {
            int row = t >> 4, cb = (t & 15) * 4;
            const float* s = Bbase + (size_t)(k0 + row) * Dm + cb;
            float4 v = *(const float4*)s;
            Bs[row][cb+0] = TF32(v.x); Bs[row][cb+1] = TF32(v.y);
            Bs[row][cb+2] = TF32(v.z); Bs[row][cb+3] = TF32(v.w);
        }
        __syncthreads();
#pragma unroll
        for (int ks = 0; ks < 16; ks += 8) {
            wmma::fragment<wmma::matrix_a, 16, 16, 8, wmma::precision::tf32,
                           wmma::row_major> af[2];
            wmma::fragment<wmma::matrix_b, 16, 16, 8, wmma::precision::tf32,
                           wmma::row_major> bf[2];
#pragma unroll
            for (int i = 0; i < 2; i++)
                wmma::load_matrix_sync(af[i], &As[wm + i*16][ks], 24);
#pragma unroll
            for (int j = 0; j < 2; j++)
                wmma::load_matrix_sync(bf[j], &Bs[ks][wn + j*16], 72);
#pragma unroll
            for (int i = 0; i < 2; i++)
#pragma unroll
                for (int j = 0; j < 2; j++)
                    wmma::mma_sync(acc[i][j], af[i], bf[j], acc[i][j]);
        }
        __syncthreads();
    }

#pragma unroll
    for (int i = 0; i < 2; i++)
#pragma unroll
        for (int j = 0; j < 2; j++)
            wmma::store_matrix_sync(
                &Cb[(size_t)(i0 + wm + i*16) * Dm + wn + j*16],
                acc[i][j], Dm, wmma::mem_row_major);
}

// ---------------- row softmax in-place, row length 2048 ---------------------
__global__ void __launch_bounds__(256) softmax_rows(float* __restrict__ aw)
{
    const size_t row = blockIdx.x;
    float* p = aw + row * Sq;
    const int t = threadIdx.x;
    __shared__ float red[8];

    float v[8];
#pragma unroll
    for (int i = 0; i < 8; i++) v[i] = p[t + i*256];

    float mx = v[0];
#pragma unroll
    for (int i = 1; i < 8; i++) mx = fmaxf(mx, v[i]);
#pragma unroll
    for (int o = 16; o; o >>= 1) mx = fmaxf(mx, __shfl_xor_sync(0xffffffffu, mx, o));
    if ((t & 31) == 0) red[t >> 5] = mx;
    __syncthreads();
    mx = red[0];
#pragma unroll
    for (int w = 1; w < 8; w++) mx = fmaxf(mx, red[w]);

    float sum = 0.f;
#pragma unroll
    for (int i = 0; i < 8; i++) { v[i] = __expf(v[i] - mx); sum += v[i]; }
#pragma unroll
    for (int o = 16; o; o >>= 1) sum += __shfl_xor_sync(0xffffffffu, sum, o);
    __syncthreads();
    if ((t & 31) == 0) red[t >> 5] = sum;
    __syncthreads();
    sum = red[0];
#pragma unroll
    for (int w = 1; w < 8; w++) sum += red[w];

    const float inv = 1.f / sum;
#pragma unroll
    for (int i = 0; i < 8; i++) p[t + i*256] = v[i] * inv;
}

// ---------------- residual add + layernorm over last dim (512) --------------
__global__ void __launch_bounds__(128) add_ln(
    const float* __restrict__ a, const float* __restrict__ r,
    const float* __restrict__ g, const float* __restrict__ be,
    float* __restrict__ out)
{
    const size_t row = blockIdx.x;
    const int t = threadIdx.x;
    __shared__ float red[4];

    float4 va = *(const float4*)&a[row * Dm + t*4];
    float4 vr = *(const float4*)&r[row * Dm + t*4];
    float x0 = va.x + vr.x, x1 = va.y + vr.y, x2 = va.z + vr.z, x3 = va.w + vr.w;

    float s = x0 + x1 + x2 + x3;
#pragma unroll
    for (int o = 16; o; o >>= 1) s += __shfl_xor_sync(0xffffffffu, s, o);
    if ((t & 31) == 0) red[t >> 5] = s;
    __syncthreads();
    float mean = (red[0] + red[1] + red[2] + red[3]) * (1.f / 512.f);

    float d0 = x0 - mean, d1 = x1 - mean, d2 = x2 - mean, d3 = x3 - mean;
    float vs = d0*d0 + d1*d1 + d2*d2 + d3*d3;
#pragma unroll
    for (int o = 16; o; o >>= 1) vs += __shfl_xor_sync(0xffffffffu, vs, o);
    __syncthreads();
    if ((t & 31) == 0) red[t >> 5] = vs;
    __syncthreads();
    float var = (red[0] + red[1] + red[2] + red[3]) * (1.f / 512.f);
    float rstd = rsqrtf(var + 1e-6f);

    float4 vg = *(const float4*)&g[t*4];
    float4 vb = *(const float4*)&be[t*4];
    float4 o4;
    o4.x = d0 * rstd * vg.x + vb.x;
    o4.y = d1 * rstd * vg.y + vb.y;
    o4.z = d2 * rstd * vg.z + vb.z;
    o4.w = d3 * rstd * vg.w + vb.w;
    *(float4*)&out[row * Dm + t*4] = o4;
}

// ---------------- launch ----------------------------------------------------
extern "C" void kernel_launch(void* const* d_in, const int* in_sizes, int n_in,
                              void* d_out, int out_size)
{
    const float* x    = (const float*)d_in[0];
    const float* enc  = (const float*)d_in[1];
    const float* wq1 = (const float*)d_in[3],  *bq1 = (const float*)d_in[4];
    const float* wk1 = (const float*)d_in[5],  *bk1 = (const float*)d_in[6];
    const float* wv1 = (const float*)d_in[7],  *bv1 = (const float*)d_in[8];
    const float* wo1 = (const float*)d_in[9],  *bo1 = (const float*)d_in[10];
    const float* wq2 = (const float*)d_in[11], *bq2 = (const float*)d_in[12];
    const float* wk2 = (const float*)d_in[13], *bk2 = (const float*)d_in[14];
    const float* wv2 = (const float*)d_in[15], *bv2 = (const float*)d_in[16];
    const float* wo2 = (const float*)d_in[17], *bo2 = (const float*)d_in[18];
    const float* wf1 = (const float*)d_in[19], *bf1 = (const float*)d_in[20];
    const float* wf2 = (const float*)d_in[21], *bf2 = (const float*)d_in[22];
    const float* g1 = (const float*)d_in[23], *be1 = (const float*)d_in[24];
    const float* g2 = (const float*)d_in[25], *be2 = (const float*)d_in[26];
    const float* g3 = (const float*)d_in[27], *be3 = (const float*)d_in[28];

    float* out3 = (float*)d_out;
    float* aw1  = out3 + (size_t)NB * Sq * Dm;
    float* aw2  = aw1  + (size_t)NB * NH * Sq * Sq;

    float *q, *k, *v, *t0, *o1, *o2, *ffh;
    cudaGetSymbolAddress((void**)&q,   g_q);
    cudaGetSymbolAddress((void**)&k,   g_k);
    cudaGetSymbolAddress((void**)&v,   g_v);
    cudaGetSymbolAddress((void**)&t0,  g_t0);
    cudaGetSymbolAddress((void**)&o1,  g_o1);
    cudaGetSymbolAddress((void**)&o2,  g_o2);
    cudaGetSymbolAddress((void**)&ffh, g_ffh);

    const int SMEM_LOG = 2 * 128 * 72 * 4;   // 73728
    cudaFuncSetAttribute(wm_logits, cudaFuncAttributeMaxDynamicSharedMemorySize,
                         SMEM_LOG);

    const dim3 gProj(Dm / 128, MROWS / 128);        // (4, 32)
    const dim3 gFF1(FFd / 128, MROWS / 128);        // (16, 32)
    const dim3 gLog(Sq / 128, Sq / 128, NB * NH);   // (16, 16, 16)
    const dim3 gAV(Sq / 128, NB * NH);              // (16, 16)

    // ---- self attention ----
    wm_gemm<false><<<gProj, 256>>>(x, wq1, bq1, q, MROWS, Dm, Dm);
    wm_gemm<false><<<gProj, 256>>>(x, wk1, bk1, k, MROWS, Dm, Dm);
    wm_gemm<false><<<gProj, 256>>>(x, wv1, bv1, v, MROWS, Dm, Dm);
    wm_logits<<<gLog, 256, SMEM_LOG>>>(q, k, aw1, 1);
    softmax_rows<<<NB * NH * Sq, 256>>>(aw1);
    wm_av<<<gAV, 256>>>(aw1, v, t0);
    wm_gemm<false><<<gProj, 256>>>(t0, wo1, bo1, q, MROWS, Dm, Dm);
    add_ln<<<MROWS, 128>>>(q, x, g1, be1, o1);

    // ---- cross attention ----
    wm_gemm<false><<<gProj, 256>>>(o1, wq2, bq2, q, MROWS, Dm, Dm);
    wm_gemm<false><<<gProj, 256>>>(enc, wk2, bk2, k, MROWS, Dm, Dm);
    wm_gemm<false><<<gProj, 256>>>(enc, wv2, bv2, v, MROWS, Dm, Dm);
    wm_logits<<<gLog, 256, SMEM_LOG>>>(q, k, aw2, 0);
    softmax_rows<<<NB * NH * Sq, 256>>>(aw2);
    wm_av<<<gAV, 256>>>(aw2, v, t0);
    wm_gemm<false><<<gProj, 256>>>(t0, wo2, bo2, q, MROWS, Dm, Dm);
    add_ln<<<MROWS, 128>>>(q, o1, g2, be2, o2);

    // ---- FFN ----
    wm_gemm<true ><<<gFF1, 256>>>(o2, wf1, bf1, ffh, MROWS, FFd, Dm);
    wm_gemm<false><<<gProj, 256>>>(ffh, wf2, bf2, t0, MROWS, Dm, FFd);
    add_ln<<<MROWS, 128>>>(t0, o2, g3, be3, out3);
}

// round 5
// speedup vs baseline: 1.9740x; 1.3797x over previous
#include <cuda_runtime.h>
#include <math.h>
#include <stdint.h>
#include <mma.h>

using namespace nvcuda;

// Problem constants
#define Sq   2048
#define Dm   512
#define NH   8
#define DKh  64
#define NB   2
#define FFd  2048
#define MROWS (NB*Sq)   // 4096

// ---------------- scratch (static device globals; no allocs) ----------------
__device__ float g_q  [MROWS*Dm];
__device__ float g_k  [MROWS*Dm];
__device__ float g_v  [MROWS*Dm];
__device__ float g_t0 [MROWS*Dm];
__device__ float g_o1 [MROWS*Dm];
__device__ float g_o2 [MROWS*Dm];
__device__ float g_ffh[MROWS*FFd];

// ---------------- cp.async helpers ------------------------------------------
__device__ __forceinline__ void cp16(const void* dst, const void* src) {
    uint32_t d = (uint32_t)__cvta_generic_to_shared(dst);
    asm volatile("cp.async.cg.shared.global [%0], [%1], 16;" :: "r"(d), "l"(src));
}
#define CP_COMMIT() asm volatile("cp.async.commit_group;" ::: "memory")
#define CP_WAIT1()  asm volatile("cp.async.wait_group 1;" ::: "memory")
#define CP_WAIT0()  asm volatile("cp.async.wait_group 0;" ::: "memory")

// =============== shared GEMM body: C = A[.,K] @ B[K,N] + bias ================
// BM=128, BN=128, BK=16, 2-stage cp.async pipeline, 256 threads
__device__ __forceinline__ void gemm_body(
    const float* __restrict__ A, const float* __restrict__ B,
    const float* __restrict__ bias, float* __restrict__ C,
    int N, int K, int m0, int n0, bool relu, char* sm)
{
    float (*As)[128][24] = (float(*)[128][24])sm;                 // 2 x 12288
    float (*Bs)[16][136] = (float(*)[16][136])(sm + 24576);       // 2 x 8704
    float (*BiasS)[136]  = (float(*)[136])(sm + 41984);           // 8704

    const int t = threadIdx.x, wid = t >> 5;
    const int wm = (wid & 3) * 32, wn = (wid >> 2) * 64;

    {
        int col = t & 127, r0 = (t >> 7) * 8;
        float bv = bias[n0 + col];
#pragma unroll
        for (int r = 0; r < 8; r++) BiasS[r0 + r][col] = bv;
    }
    __syncthreads();

    wmma::fragment<wmma::accumulator, 16, 16, 8, float> acc[2][4];
#pragma unroll
    for (int i = 0; i < 2; i++)
#pragma unroll
        for (int j = 0; j < 4; j++)
            wmma::load_matrix_sync(acc[i][j], &BiasS[0][wn + j*16], 136,
                                   wmma::mem_row_major);

    const float* Ab = A + (size_t)m0 * K;
    const float* Bb = B + n0;

    // prefetch stage 0
#pragma unroll
    for (int c = t; c < 512; c += 256) {
        int row = c >> 2, sg = c & 3;
        cp16(&As[0][row][sg*4], Ab + (size_t)row * K + sg*4);
    }
#pragma unroll
    for (int c = t; c < 512; c += 256) {
        int row = c >> 5, sg = c & 31;
        cp16(&Bs[0][row][sg*4], Bb + (size_t)row * N + sg*4);
    }
    CP_COMMIT();

    const int KT = K >> 4;
    for (int kt = 0; kt < KT; kt++) {
        const int cur = kt & 1;
        if (kt + 1 < KT) {
            const int k0 = (kt + 1) << 4;
#pragma unroll
            for (int c = t; c < 512; c += 256) {
                int row = c >> 2, sg = c & 3;
                cp16(&As[cur^1][row][sg*4], Ab + (size_t)row * K + k0 + sg*4);
            }
#pragma unroll
            for (int c = t; c < 512; c += 256) {
                int row = c >> 5, sg = c & 31;
                cp16(&Bs[cur^1][row][sg*4], Bb + (size_t)(k0 + row) * N + sg*4);
            }
            CP_COMMIT();
            CP_WAIT1();
        } else {
            CP_WAIT0();
        }
        __syncthreads();
#pragma unroll
        for (int ks = 0; ks < 16; ks += 8) {
            wmma::fragment<wmma::matrix_a, 16, 16, 8, wmma::precision::tf32,
                           wmma::row_major> af[2];
            wmma::fragment<wmma::matrix_b, 16, 16, 8, wmma::precision::tf32,
                           wmma::row_major> bf[4];
#pragma unroll
            for (int i = 0; i < 2; i++)
                wmma::load_matrix_sync(af[i], &As[cur][wm + i*16][ks], 24);
#pragma unroll
            for (int j = 0; j < 4; j++)
                wmma::load_matrix_sync(bf[j], &Bs[cur][ks][wn + j*16], 136);
#pragma unroll
            for (int i = 0; i < 2; i++)
#pragma unroll
                for (int j = 0; j < 4; j++)
                    wmma::mma_sync(acc[i][j], af[i], bf[j], acc[i][j]);
        }
        __syncthreads();
    }

#pragma unroll
    for (int i = 0; i < 2; i++)
#pragma unroll
        for (int j = 0; j < 4; j++) {
            if (relu) {
#pragma unroll
                for (int e = 0; e < acc[i][j].num_elements; e++)
                    acc[i][j].x[e] = fmaxf(acc[i][j].x[e], 0.f);
            }
            wmma::store_matrix_sync(
                &C[(size_t)(m0 + wm + i*16) * N + n0 + wn + j*16],
                acc[i][j], N, wmma::mem_row_major);
        }
}

template<bool RELU>
__global__ void __launch_bounds__(256, 2) wm_gemm(
    const float* __restrict__ A, const float* __restrict__ B,
    const float* __restrict__ bias, float* __restrict__ C, int N, int K)
{
    extern __shared__ char sm[];
    gemm_body(A, B, bias, C, N, K, blockIdx.y * 128, blockIdx.x * 128, RELU, sm);
}

// fused triple GEMM (shares grid across 3 weight matrices, N=512 each)
__global__ void __launch_bounds__(256, 2) wm_gemm3(
    const float* __restrict__ A0, const float* __restrict__ A1,
    const float* __restrict__ A2,
    const float* __restrict__ B0, const float* __restrict__ B1,
    const float* __restrict__ B2,
    const float* __restrict__ b0, const float* __restrict__ b1,
    const float* __restrict__ b2,
    float* __restrict__ C0, float* __restrict__ C1, float* __restrict__ C2,
    int N, int K)
{
    extern __shared__ char sm[];
    const int mat = blockIdx.x >> 2;
    const float* A = (mat == 0) ? A0 : (mat == 1) ? A1 : A2;
    const float* B = (mat == 0) ? B0 : (mat == 1) ? B1 : B2;
    const float* bias = (mat == 0) ? b0 : (mat == 1) ? b1 : b2;
    float* C = (mat == 0) ? C0 : (mat == 1) ? C1 : C2;
    gemm_body(A, B, bias, C, N, K, blockIdx.y * 128, (blockIdx.x & 3) * 128,
              false, sm);
}

// ============ WMMA tf32 logits: scale * Q @ K^T (+causal mask) ==============
__global__ void __launch_bounds__(256, 2) wm_logits(
    const float* __restrict__ Q, const float* __restrict__ Km,
    float* __restrict__ out, int causal)
{
    extern __shared__ char smc[];
    float (*Qs)[68] = (float(*)[68])smc;                 // 128x68x4 = 34816
    float (*Ks)[68] = (float(*)[68])(smc + 34816);       // 34816
    float (*St)[136] = (float(*)[136])smc;               // reuse: 69632

    const int bh = blockIdx.z;
    const int b = bh >> 3, h = bh & 7;
    const int i0 = blockIdx.y * 128, j0 = blockIdx.x * 128;
    const int t = threadIdx.x, wid = t >> 5;
    float* Ob = out + (size_t)bh * Sq * Sq;

    if (causal && j0 > i0 + 127) {
        const float4 neg = make_float4(-1e9f, -1e9f, -1e9f, -1e9f);
        for (int idx = t; idx < 4096; idx += 256) {
            int row = idx >> 5, c4 = idx & 31;
            *(float4*)&Ob[(size_t)(i0 + row) * Sq + j0 + c4 * 4] = neg;
        }
        return;
    }

    const float* Qb = Q  + (size_t)b * Sq * Dm + h * DKh + (size_t)i0 * Dm;
    const float* Kb = Km + (size_t)b * Sq * Dm + h * DKh + (size_t)j0 * Dm;

#pragma unroll
    for (int c = t; c < 2048; c += 256) {
        int row = c >> 4, sg = c & 15;
        cp16(&Qs[row][sg*4], Qb + (size_t)row * Dm + sg*4);
    }
#pragma unroll
    for (int c = t; c < 2048; c += 256) {
        int row = c >> 4, sg = c & 15;
        cp16(&Ks[row][sg*4], Kb + (size_t)row * Dm + sg*4);
    }
    CP_COMMIT();
    CP_WAIT0();
    __syncthreads();

    const int wm = (wid & 3) * 32, wn = (wid >> 2) * 64;
    wmma::fragment<wmma::accumulator, 16, 16, 8, float> acc[2][4];
#pragma unroll
    for (int i = 0; i < 2; i++)
#pragma unroll
        for (int j = 0; j < 4; j++) wmma::fill_fragment(acc[i][j], 0.f);

#pragma unroll
    for (int ks = 0; ks < 64; ks += 8) {
        wmma::fragment<wmma::matrix_a, 16, 16, 8, wmma::precision::tf32,
                       wmma::row_major> af[2];
        wmma::fragment<wmma::matrix_b, 16, 16, 8, wmma::precision::tf32,
                       wmma::col_major> bf[4];
#pragma unroll
        for (int i = 0; i < 2; i++)
            wmma::load_matrix_sync(af[i], &Qs[wm + i*16][ks], 68);
#pragma unroll
        for (int j = 0; j < 4; j++)
            wmma::load_matrix_sync(bf[j], &Ks[wn + j*16][ks], 68);
#pragma unroll
        for (int i = 0; i < 2; i++)
#pragma unroll
            for (int j = 0; j < 4; j++)
                wmma::mma_sync(acc[i][j], af[i], bf[j], acc[i][j]);
    }
    __syncthreads();   // done with Qs/Ks; reuse as staging

#pragma unroll
    for (int i = 0; i < 2; i++)
#pragma unroll
        for (int j = 0; j < 4; j++)
            wmma::store_matrix_sync(&St[wm + i*16][wn + j*16], acc[i][j], 136,
                                    wmma::mem_row_major);
    __syncthreads();

    // epilogue: scale + causal, coalesced global write
    {
        int row = t >> 1, cb = (t & 1) * 64;
        int gi = i0 + row;
        float* orow = Ob + (size_t)gi * Sq + j0 + cb;
#pragma unroll
        for (int u = 0; u < 16; u++) {
            float4 v;
            int gj = j0 + cb + u * 4;
            v.x = St[row][cb + u*4 + 0] * 0.125f + ((causal && gj+0 > gi) ? -1e9f : 0.f);
            v.y = St[row][cb + u*4 + 1] * 0.125f + ((causal && gj+1 > gi) ? -1e9f : 0.f);
            v.z = St[row][cb + u*4 + 2] * 0.125f + ((causal && gj+2 > gi) ? -1e9f : 0.f);
            v.w = St[row][cb + u*4 + 3] * 0.125f + ((causal && gj+3 > gi) ? -1e9f : 0.f);
            *(float4*)(orow + u * 4) = v;
        }
    }
}

// ============ WMMA tf32 AV (pipelined): out = aw @ V_head ===================
// BM=128, BN=64, BK=16, 2-stage cp.async, 256 threads
__global__ void __launch_bounds__(256, 2) wm_av(
    const float* __restrict__ aw, const float* __restrict__ V,
    float* __restrict__ out)
{
    __shared__ float As[2][128][24];   // 24576
    __shared__ float Bs[2][16][72];    // 9216

    const int bh = blockIdx.y;
    const int b = bh >> 3, h = bh & 7;
    const int i0 = blockIdx.x * 128;
    const int t = threadIdx.x, wid = t >> 5;

    const float* Ab = aw + (size_t)bh * Sq * Sq + (size_t)i0 * Sq;
    const float* Bb = V + (size_t)b * Sq * Dm + h * DKh;
    float*       Cb = out + (size_t)b * Sq * Dm + h * DKh;

    const int wm = (wid & 3) * 32, wn = (wid >> 2) * 32;
    wmma::fragment<wmma::accumulator, 16, 16, 8, float> acc[2][2];
#pragma unroll
    for (int i = 0; i < 2; i++)
#pragma unroll
        for (int j = 0; j < 2; j++) wmma::fill_fragment(acc[i][j], 0.f);

    // prefetch stage 0
#pragma unroll
    for (int c = t; c < 512; c += 256) {
        int row = c >> 2, sg = c & 3;
        cp16(&As[0][row][sg*4], Ab + (size_t)row * Sq + sg*4);
    }
    {
        int row = t >> 4, sg = t & 15;
        cp16(&Bs[0][row][sg*4], Bb + (size_t)row * Dm + sg*4);
    }
    CP_COMMIT();

    const int KT = Sq >> 4;   // 128
    for (int kt = 0; kt < KT; kt++) {
        const int cur = kt & 1;
        if (kt + 1 < KT) {
            const int k0 = (kt + 1) << 4;
#pragma unroll
            for (int c = t; c < 512; c += 256) {
                int row = c >> 2, sg = c & 3;
                cp16(&As[cur^1][row][sg*4], Ab + (size_t)row * Sq + k0 + sg*4);
            }
            {
                int row = t >> 4, sg = t & 15;
                cp16(&Bs[cur^1][row][sg*4], Bb + (size_t)(k0 + row) * Dm + sg*4);
            }
            CP_COMMIT();
            CP_WAIT1();
        } else {
            CP_WAIT0();
        }
        __syncthreads();
#pragma unroll
        for (int ks = 0; ks < 16; ks += 8) {
            wmma::fragment<wmma::matrix_a, 16, 16, 8, wmma::precision::tf32,
                           wmma::row_major> af[2];
            wmma::fragment<wmma::matrix_b, 16, 16, 8, wmma::precision::tf32,
                           wmma::row_major> bf[2];
#pragma unroll
            for (int i = 0; i < 2; i++)
                wmma::load_matrix_sync(af[i], &As[cur][wm + i*16][ks], 24);
#pragma unroll
            for (int j = 0; j < 2; j++)
                wmma::load_matrix_sync(bf[j], &Bs[cur][ks][wn + j*16], 72);
#pragma unroll
            for (int i = 0; i < 2; i++)
#pragma unroll
                for (int j = 0; j < 2; j++)
                    wmma::mma_sync(acc[i][j], af[i], bf[j], acc[i][j]);
        }
        __syncthreads();
    }

#pragma unroll
    for (int i = 0; i < 2; i++)
#pragma unroll
        for (int j = 0; j < 2; j++)
            wmma::store_matrix_sync(
                &Cb[(size_t)(i0 + wm + i*16) * Dm + wn + j*16],
                acc[i][j], Dm, wmma::mem_row_major);
}

// ---------------- row softmax in-place, row length 2048 ---------------------
__global__ void __launch_bounds__(256) softmax_rows(float* __restrict__ aw)
{
    const size_t row = blockIdx.x;
    float* p = aw + row * Sq;
    const int t = threadIdx.x;
    __shared__ float red[8];

    float v[8];
#pragma unroll
    for (int i = 0; i < 8; i++) v[i] = p[t + i*256];

    float mx = v[0];
#pragma unroll
    for (int i = 1; i < 8; i++) mx = fmaxf(mx, v[i]);
#pragma unroll
    for (int o = 16; o; o >>= 1) mx = fmaxf(mx, __shfl_xor_sync(0xffffffffu, mx, o));
    if ((t & 31) == 0) red[t >> 5] = mx;
    __syncthreads();
    mx = red[0];
#pragma unroll
    for (int w = 1; w < 8; w++) mx = fmaxf(mx, red[w]);

    float sum = 0.f;
#pragma unroll
    for (int i = 0; i < 8; i++) { v[i] = __expf(v[i] - mx); sum += v[i]; }
#pragma unroll
    for (int o = 16; o; o >>= 1) sum += __shfl_xor_sync(0xffffffffu, sum, o);
    __syncthreads();
    if ((t & 31) == 0) red[t >> 5] = sum;
    __syncthreads();
    sum = red[0];
#pragma unroll
    for (int w = 1; w < 8; w++) sum += red[w];

    const float inv = 1.f / sum;
#pragma unroll
    for (int i = 0; i < 8; i++) p[t + i*256] = v[i] * inv;
}

// ---------------- residual add + layernorm over last dim (512) --------------
__global__ void __launch_bounds__(128) add_ln(
    const float* __restrict__ a, const float* __restrict__ r,
    const float* __restrict__ g, const float* __restrict__ be,
    float* __restrict__ out)
{
    const size_t row = blockIdx.x;
    const int t = threadIdx.x;
    __shared__ float red[4];

    float4 va = *(const float4*)&a[row * Dm + t*4];
    float4 vr = *(const float4*)&r[row * Dm + t*4];
    float x0 = va.x + vr.x, x1 = va.y + vr.y, x2 = va.z + vr.z, x3 = va.w + vr.w;

    float s = x0 + x1 + x2 + x3;
#pragma unroll
    for (int o = 16; o; o >>= 1) s += __shfl_xor_sync(0xffffffffu, s, o);
    if ((t & 31) == 0) red[t >> 5] = s;
    __syncthreads();
    float mean = (red[0] + red[1] + red[2] + red[3]) * (1.f / 512.f);

    float d0 = x0 - mean, d1 = x1 - mean, d2 = x2 - mean, d3 = x3 - mean;
    float vs = d0*d0 + d1*d1 + d2*d2 + d3*d3;
#pragma unroll
    for (int o = 16; o; o >>= 1) vs += __shfl_xor_sync(0xffffffffu, vs, o);
    __syncthreads();
    if ((t & 31) == 0) red[t >> 5] = vs;
    __syncthreads();
    float var = (red[0] + red[1] + red[2] + red[3]) * (1.f / 512.f);
    float rstd = rsqrtf(var + 1e-6f);

    float4 vg = *(const float4*)&g[t*4];
    float4 vb = *(const float4*)&be[t*4];
    float4 o4;
    o4.x = d0 * rstd * vg.x + vb.x;
    o4.y = d1 * rstd * vg.y + vb.y;
    o4.z = d2 * rstd * vg.z + vb.z;
    o4.w = d3 * rstd * vg.w + vb.w;
    *(float4*)&out[row * Dm + t*4] = o4;
}

// ---------------- launch ----------------------------------------------------
extern "C" void kernel_launch(void* const* d_in, const int* in_sizes, int n_in,
                              void* d_out, int out_size)
{
    const float* x    = (const float*)d_in[0];
    const float* enc  = (const float*)d_in[1];
    const float* wq1 = (const float*)d_in[3],  *bq1 = (const float*)d_in[4];
    const float* wk1 = (const float*)d_in[5],  *bk1 = (const float*)d_in[6];
    const float* wv1 = (const float*)d_in[7],  *bv1 = (const float*)d_in[8];
    const float* wo1 = (const float*)d_in[9],  *bo1 = (const float*)d_in[10];
    const float* wq2 = (const float*)d_in[11], *bq2 = (const float*)d_in[12];
    const float* wk2 = (const float*)d_in[13], *bk2 = (const float*)d_in[14];
    const float* wv2 = (const float*)d_in[15], *bv2 = (const float*)d_in[16];
    const float* wo2 = (const float*)d_in[17], *bo2 = (const float*)d_in[18];
    const float* wf1 = (const float*)d_in[19], *bf1 = (const float*)d_in[20];
    const float* wf2 = (const float*)d_in[21], *bf2 = (const float*)d_in[22];
    const float* g1 = (const float*)d_in[23], *be1 = (const float*)d_in[24];
    const float* g2 = (const float*)d_in[25], *be2 = (const float*)d_in[26];
    const float* g3 = (const float*)d_in[27], *be3 = (const float*)d_in[28];

    float* out3 = (float*)d_out;
    float* aw1  = out3 + (size_t)NB * Sq * Dm;
    float* aw2  = aw1  + (size_t)NB * NH * Sq * Sq;

    float *q, *k, *v, *t0, *o1, *o2, *ffh;
    cudaGetSymbolAddress((void**)&q,   g_q);
    cudaGetSymbolAddress((void**)&k,   g_k);
    cudaGetSymbolAddress((void**)&v,   g_v);
    cudaGetSymbolAddress((void**)&t0,  g_t0);
    cudaGetSymbolAddress((void**)&o1,  g_o1);
    cudaGetSymbolAddress((void**)&o2,  g_o2);
    cudaGetSymbolAddress((void**)&ffh, g_ffh);

    const int SMEM_GEMM = 50688;
    const int SMEM_LOG  = 69632;
    cudaFuncSetAttribute(wm_gemm<false>, cudaFuncAttributeMaxDynamicSharedMemorySize, SMEM_GEMM);
    cudaFuncSetAttribute(wm_gemm<true>,  cudaFuncAttributeMaxDynamicSharedMemorySize, SMEM_GEMM);
    cudaFuncSetAttribute(wm_gemm3,       cudaFuncAttributeMaxDynamicSharedMemorySize, SMEM_GEMM);
    cudaFuncSetAttribute(wm_logits,      cudaFuncAttributeMaxDynamicSharedMemorySize, SMEM_LOG);

    const dim3 gProj(Dm / 128, MROWS / 128);        // (4, 32)
    const dim3 gQKV(12, MROWS / 128);               // (12, 32)
    const dim3 gFF1(FFd / 128, MROWS / 128);        // (16, 32)
    const dim3 gLog(Sq / 128, Sq / 128, NB * NH);   // (16, 16, 16)
    const dim3 gAV(Sq / 128, NB * NH);              // (16, 16)

    // ---- self attention ----
    wm_gemm3<<<gQKV, 256, SMEM_GEMM>>>(x, x, x, wq1, wk1, wv1,
                                       bq1, bk1, bv1, q, k, v, Dm, Dm);
    wm_logits<<<gLog, 256, SMEM_LOG>>>(q, k, aw1, 1);
    softmax_rows<<<NB * NH * Sq, 256>>>(aw1);
    wm_av<<<gAV, 256>>>(aw1, v, t0);
    wm_gemm<false><<<gProj, 256, SMEM_GEMM>>>(t0, wo1, bo1, q, Dm, Dm);
    add_ln<<<MROWS, 128>>>(q, x, g1, be1, o1);

    // ---- cross attention ----
    wm_gemm3<<<gQKV, 256, SMEM_GEMM>>>(o1, enc, enc, wq2, wk2, wv2,
                                       bq2, bk2, bv2, q, k, v, Dm, Dm);
    wm_logits<<<gLog, 256, SMEM_LOG>>>(q, k, aw2, 0);
    softmax_rows<<<NB * NH * Sq, 256>>>(aw2);
    wm_av<<<gAV, 256>>>(aw2, v, t0);
    wm_gemm<false><<<gProj, 256, SMEM_GEMM>>>(t0, wo2, bo2, q, Dm, Dm);
    add_ln<<<MROWS, 128>>>(q, o1, g2, be2, o2);

    // ---- FFN ----
    wm_gemm<true ><<<gFF1, 256, SMEM_GEMM>>>(o2, wf1, bf1, ffh, FFd, Dm);
    wm_gemm<false><<<gProj, 256, SMEM_GEMM>>>(ffh, wf2, bf2, t0, Dm, FFd);
    add_ln<<<MROWS, 128>>>(t0, o2, g3, be3, out3);
}

// round 6
// speedup vs baseline: 2.0260x; 1.0263x over previous
#include <cuda_runtime.h>
#include <math.h>
#include <stdint.h>
#include <mma.h>

using namespace nvcuda;

// Problem constants
#define Sq   2048
#define Dm   512
#define NH   8
#define DKh  64
#define NB   2
#define FFd  2048
#define MROWS (NB*Sq)   // 4096

// ---------------- scratch (static device globals; no allocs) ----------------
__device__ float g_q  [MROWS*Dm];
__device__ float g_k  [MROWS*Dm];
__device__ float g_v  [MROWS*Dm];
__device__ float g_t0 [MROWS*Dm];
__device__ float g_o1 [MROWS*Dm];
__device__ float g_o2 [MROWS*Dm];
__device__ float g_ffh[MROWS*FFd];
__device__ float g_part[(size_t)NB*NH*Sq*16];   // row partial sums (2MB)

// ---------------- cp.async helpers ------------------------------------------
__device__ __forceinline__ void cp16(const void* dst, const void* src) {
    uint32_t d = (uint32_t)__cvta_generic_to_shared(dst);
    asm volatile("cp.async.cg.shared.global [%0], [%1], 16;" :: "r"(d), "l"(src));
}
#define CP_COMMIT() asm volatile("cp.async.commit_group;" ::: "memory")
#define CP_WAIT1()  asm volatile("cp.async.wait_group 1;" ::: "memory")
#define CP_WAIT0()  asm volatile("cp.async.wait_group 0;" ::: "memory")

// =============== shared GEMM body: C = A[.,K] @ B[K,N] + bias ================
// BM=128, BN=128, BK=16, 2-stage cp.async pipeline, 256 threads
__device__ __forceinline__ void gemm_body(
    const float* __restrict__ A, const float* __restrict__ B,
    const float* __restrict__ bias, float* __restrict__ C,
    int N, int K, int m0, int n0, bool relu, char* sm)
{
    float (*As)[128][24] = (float(*)[128][24])sm;                 // 2 x 12288
    float (*Bs)[16][136] = (float(*)[16][136])(sm + 24576);       // 2 x 8704
    float (*BiasS)[136]  = (float(*)[136])(sm + 41984);           // 8704

    const int t = threadIdx.x, wid = t >> 5;
    const int wm = (wid & 3) * 32, wn = (wid >> 2) * 64;

    {
        int col = t & 127, r0 = (t >> 7) * 8;
        float bv = bias[n0 + col];
#pragma unroll
        for (int r = 0; r < 8; r++) BiasS[r0 + r][col] = bv;
    }
    __syncthreads();

    wmma::fragment<wmma::accumulator, 16, 16, 8, float> acc[2][4];
#pragma unroll
    for (int i = 0; i < 2; i++)
#pragma unroll
        for (int j = 0; j < 4; j++)
            wmma::load_matrix_sync(acc[i][j], &BiasS[0][wn + j*16], 136,
                                   wmma::mem_row_major);

    const float* Ab = A + (size_t)m0 * K;
    const float* Bb = B + n0;

#pragma unroll
    for (int c = t; c < 512; c += 256) {
        int row = c >> 2, sg = c & 3;
        cp16(&As[0][row][sg*4], Ab + (size_t)row * K + sg*4);
    }
#pragma unroll
    for (int c = t; c < 512; c += 256) {
        int row = c >> 5, sg = c & 31;
        cp16(&Bs[0][row][sg*4], Bb + (size_t)row * N + sg*4);
    }
    CP_COMMIT();

    const int KT = K >> 4;
    for (int kt = 0; kt < KT; kt++) {
        const int cur = kt & 1;
        if (kt + 1 < KT) {
            const int k0 = (kt + 1) << 4;
#pragma unroll
            for (int c = t; c < 512; c += 256) {
                int row = c >> 2, sg = c & 3;
                cp16(&As[cur^1][row][sg*4], Ab + (size_t)row * K + k0 + sg*4);
            }
#pragma unroll
            for (int c = t; c < 512; c += 256) {
                int row = c >> 5, sg = c & 31;
                cp16(&Bs[cur^1][row][sg*4], Bb + (size_t)(k0 + row) * N + sg*4);
            }
            CP_COMMIT();
            CP_WAIT1();
        } else {
            CP_WAIT0();
        }
        __syncthreads();
#pragma unroll
        for (int ks = 0; ks < 16; ks += 8) {
            wmma::fragment<wmma::matrix_a, 16, 16, 8, wmma::precision::tf32,
                           wmma::row_major> af[2];
            wmma::fragment<wmma::matrix_b, 16, 16, 8, wmma::precision::tf32,
                           wmma::row_major> bf[4];
#pragma unroll
            for (int i = 0; i < 2; i++)
                wmma::load_matrix_sync(af[i], &As[cur][wm + i*16][ks], 24);
#pragma unroll
            for (int j = 0; j < 4; j++)
                wmma::load_matrix_sync(bf[j], &Bs[cur][ks][wn + j*16], 136);
#pragma unroll
            for (int i = 0; i < 2; i++)
#pragma unroll
                for (int j = 0; j < 4; j++)
                    wmma::mma_sync(acc[i][j], af[i], bf[j], acc[i][j]);
        }
        __syncthreads();
    }

#pragma unroll
    for (int i = 0; i < 2; i++)
#pragma unroll
        for (int j = 0; j < 4; j++) {
            if (relu) {
#pragma unroll
                for (int e = 0; e < acc[i][j].num_elements; e++)
                    acc[i][j].x[e] = fmaxf(acc[i][j].x[e], 0.f);
            }
            wmma::store_matrix_sync(
                &C[(size_t)(m0 + wm + i*16) * N + n0 + wn + j*16],
                acc[i][j], N, wmma::mem_row_major);
        }
}

template<bool RELU>
__global__ void __launch_bounds__(256, 2) wm_gemm(
    const float* __restrict__ A, const float* __restrict__ B,
    const float* __restrict__ bias, float* __restrict__ C, int N, int K)
{
    extern __shared__ char sm[];
    gemm_body(A, B, bias, C, N, K, blockIdx.y * 128, blockIdx.x * 128, RELU, sm);
}

// fused triple GEMM (shares grid across 3 weight matrices, N=512 each)
__global__ void __launch_bounds__(256, 2) wm_gemm3(
    const float* __restrict__ A0, const float* __restrict__ A1,
    const float* __restrict__ A2,
    const float* __restrict__ B0, const float* __restrict__ B1,
    const float* __restrict__ B2,
    const float* __restrict__ b0, const float* __restrict__ b1,
    const float* __restrict__ b2,
    float* __restrict__ C0, float* __restrict__ C1, float* __restrict__ C2,
    int N, int K)
{
    extern __shared__ char sm[];
    const int mat = blockIdx.x >> 2;
    const float* A = (mat == 0) ? A0 : (mat == 1) ? A1 : A2;
    const float* B = (mat == 0) ? B0 : (mat == 1) ? B1 : B2;
    const float* bias = (mat == 0) ? b0 : (mat == 1) ? b1 : b2;
    float* C = (mat == 0) ? C0 : (mat == 1) ? C1 : C2;
    gemm_body(A, B, bias, C, N, K, blockIdx.y * 128, (blockIdx.x & 3) * 128,
              false, sm);
}

// =============== BM=64 GEMM for underfilled shapes (wo, ff2) ================
__global__ void __launch_bounds__(256, 2) wm_gemm64(
    const float* __restrict__ A, const float* __restrict__ B,
    const float* __restrict__ bias, float* __restrict__ C, int N, int K)
{
    __shared__ float As[2][64][24];     // 12288
    __shared__ float Bs[2][16][136];    // 17408
    __shared__ float BiasS[16][136];    // 8704

    const int t = threadIdx.x, wid = t >> 5;
    const int m0 = blockIdx.y * 64, n0 = blockIdx.x * 128;
    const int wm = (wid & 3) * 16, wn = (wid >> 2) * 64;

    {
        int col = t & 127, r0 = (t >> 7) * 8;
        float bv = bias[n0 + col];
#pragma unroll
        for (int r = 0; r < 8; r++) BiasS[r0 + r][col] = bv;
    }
    __syncthreads();

    wmma::fragment<wmma::accumulator, 16, 16, 8, float> acc[4];
#pragma unroll
    for (int j = 0; j < 4; j++)
        wmma::load_matrix_sync(acc[j], &BiasS[0][wn + j*16], 136,
                               wmma::mem_row_major);

    const float* Ab = A + (size_t)m0 * K;
    const float* Bb = B + n0;

    {
        int row = t >> 2, sg = t & 3;
        cp16(&As[0][row][sg*4], Ab + (size_t)row * K + sg*4);
    }
#pragma unroll
    for (int c = t; c < 512; c += 256) {
        int row = c >> 5, sg = c & 31;
        cp16(&Bs[0][row][sg*4], Bb + (size_t)row * N + sg*4);
    }
    CP_COMMIT();

    const int KT = K >> 4;
    for (int kt = 0; kt < KT; kt++) {
        const int cur = kt & 1;
        if (kt + 1 < KT) {
            const int k0 = (kt + 1) << 4;
            {
                int row = t >> 2, sg = t & 3;
                cp16(&As[cur^1][row][sg*4], Ab + (size_t)row * K + k0 + sg*4);
            }
#pragma unroll
            for (int c = t; c < 512; c += 256) {
                int row = c >> 5, sg = c & 31;
                cp16(&Bs[cur^1][row][sg*4], Bb + (size_t)(k0 + row) * N + sg*4);
            }
            CP_COMMIT();
            CP_WAIT1();
        } else {
            CP_WAIT0();
        }
        __syncthreads();
#pragma unroll
        for (int ks = 0; ks < 16; ks += 8) {
            wmma::fragment<wmma::matrix_a, 16, 16, 8, wmma::precision::tf32,
                           wmma::row_major> af;
            wmma::fragment<wmma::matrix_b, 16, 16, 8, wmma::precision::tf32,
                           wmma::row_major> bf[4];
            wmma::load_matrix_sync(af, &As[cur][wm][ks], 24);
#pragma unroll
            for (int j = 0; j < 4; j++)
                wmma::load_matrix_sync(bf[j], &Bs[cur][ks][wn + j*16], 136);
#pragma unroll
            for (int j = 0; j < 4; j++)
                wmma::mma_sync(acc[j], af, bf[j], acc[j]);
        }
        __syncthreads();
    }

#pragma unroll
    for (int j = 0; j < 4; j++)
        wmma::store_matrix_sync(&C[(size_t)(m0 + wm) * N + n0 + wn + j*16],
                                acc[j], N, wmma::mem_row_major);
}

// ===== logits+exp: E = exp(scale*Q@K^T) (masked->0) + row partial sums ======
__global__ void __launch_bounds__(256, 2) wm_logits_exp(
    const float* __restrict__ Q, const float* __restrict__ Km,
    float* __restrict__ out, float* __restrict__ part, int causal)
{
    extern __shared__ char smc[];
    float (*Qs)[68] = (float(*)[68])smc;                 // 34816
    float (*Ks)[68] = (float(*)[68])(smc + 34816);       // 34816
    float (*St)[136] = (float(*)[136])smc;               // reuse: 69632

    const int bh = blockIdx.z;
    const int b = bh >> 3, h = bh & 7;
    const int i0 = blockIdx.y * 128, j0 = blockIdx.x * 128;
    const int jt = blockIdx.x;
    const int t = threadIdx.x, wid = t >> 5;
    float* Ob = out + (size_t)bh * Sq * Sq;

    if (causal && j0 > i0 + 127) {
        // fully masked: E = 0 (this is also the final aw value here)
        const float4 zero = make_float4(0.f, 0.f, 0.f, 0.f);
        for (int idx = t; idx < 4096; idx += 256) {
            int row = idx >> 5, c4 = idx & 31;
            *(float4*)&Ob[(size_t)(i0 + row) * Sq + j0 + c4 * 4] = zero;
        }
        if (t < 128)
            part[((size_t)bh * Sq + i0 + t) * 16 + jt] = 0.f;
        return;
    }

    const float* Qb = Q  + (size_t)b * Sq * Dm + h * DKh + (size_t)i0 * Dm;
    const float* Kb = Km + (size_t)b * Sq * Dm + h * DKh + (size_t)j0 * Dm;

#pragma unroll
    for (int c = t; c < 2048; c += 256) {
        int row = c >> 4, sg = c & 15;
        cp16(&Qs[row][sg*4], Qb + (size_t)row * Dm + sg*4);
    }
#pragma unroll
    for (int c = t; c < 2048; c += 256) {
        int row = c >> 4, sg = c & 15;
        cp16(&Ks[row][sg*4], Kb + (size_t)row * Dm + sg*4);
    }
    CP_COMMIT();
    CP_WAIT0();
    __syncthreads();

    const int wm = (wid & 3) * 32, wn = (wid >> 2) * 64;
    wmma::fragment<wmma::accumulator, 16, 16, 8, float> acc[2][4];
#pragma unroll
    for (int i = 0; i < 2; i++)
#pragma unroll
        for (int j = 0; j < 4; j++) wmma::fill_fragment(acc[i][j], 0.f);

#pragma unroll
    for (int ks = 0; ks < 64; ks += 8) {
        wmma::fragment<wmma::matrix_a, 16, 16, 8, wmma::precision::tf32,
                       wmma::row_major> af[2];
        wmma::fragment<wmma::matrix_b, 16, 16, 8, wmma::precision::tf32,
                       wmma::col_major> bf[4];
#pragma unroll
        for (int i = 0; i < 2; i++)
            wmma::load_matrix_sync(af[i], &Qs[wm + i*16][ks], 68);
#pragma unroll
        for (int j = 0; j < 4; j++)
            wmma::load_matrix_sync(bf[j], &Ks[wn + j*16][ks], 68);
#pragma unroll
        for (int i = 0; i < 2; i++)
#pragma unroll
            for (int j = 0; j < 4; j++)
                wmma::mma_sync(acc[i][j], af[i], bf[j], acc[i][j]);
    }
    __syncthreads();   // done with Qs/Ks; reuse as staging

#pragma unroll
    for (int i = 0; i < 2; i++)
#pragma unroll
        for (int j = 0; j < 4; j++)
            wmma::store_matrix_sync(&St[wm + i*16][wn + j*16], acc[i][j], 136,
                                    wmma::mem_row_major);
    __syncthreads();

    // epilogue: E = exp(s/8) with causal zeros, plus per-row partial sum
    {
        int row = t >> 1, cb = (t & 1) * 64;
        int gi = i0 + row;
        float* orow = Ob + (size_t)gi * Sq + j0 + cb;
        float psum = 0.f;
#pragma unroll
        for (int u = 0; u < 16; u++) {
            float4 v;
            int gj = j0 + cb + u * 4;
            v.x = (causal && gj+0 > gi) ? 0.f : __expf(St[row][cb + u*4 + 0] * 0.125f);
            v.y = (causal && gj+1 > gi) ? 0.f : __expf(St[row][cb + u*4 + 1] * 0.125f);
            v.z = (causal && gj+2 > gi) ? 0.f : __expf(St[row][cb + u*4 + 2] * 0.125f);
            v.w = (causal && gj+3 > gi) ? 0.f : __expf(St[row][cb + u*4 + 3] * 0.125f);
            psum += v.x + v.y + v.z + v.w;
            *(float4*)(orow + u * 4) = v;
        }
        psum += __shfl_xor_sync(0xffffffffu, psum, 1);
        if ((t & 1) == 0)
            part[((size_t)bh * Sq + gi) * 16 + jt] = psum;
    }
}

// ===== AV with fused normalize: reads E, writes aw = E/sum and out = aw@V ===
__global__ void __launch_bounds__(256, 2) wm_av_norm(
    float* __restrict__ aw, const float* __restrict__ V,
    const float* __restrict__ part, float* __restrict__ out, int causal)
{
    __shared__ float As[2][128][24];   // 24576
    __shared__ float Bs[2][16][72];    // 9216
    __shared__ float invs[128];

    const int bh = blockIdx.y;
    const int b = bh >> 3, h = bh & 7;
    const int i0 = blockIdx.x * 128;
    const int t = threadIdx.x, wid = t >> 5;

    float*       Abw = aw + (size_t)bh * Sq * Sq + (size_t)i0 * Sq;
    const float* Bb  = V + (size_t)b * Sq * Dm + h * DKh;
    float*       Cb  = out + (size_t)b * Sq * Dm + h * DKh;

    // per-row inverse softmax sums (deterministic partial reduction)
    if (t < 128) {
        const float* pp = part + ((size_t)bh * Sq + i0 + t) * 16;
        float s = 0.f;
#pragma unroll
        for (int jt = 0; jt < 16; jt++) s += pp[jt];
        invs[t] = 1.f / s;
    }

    const int wm = (wid & 3) * 32, wn = (wid >> 2) * 32;
    wmma::fragment<wmma::accumulator, 16, 16, 8, float> acc[2][2];
#pragma unroll
    for (int i = 0; i < 2; i++)
#pragma unroll
        for (int j = 0; j < 2; j++) wmma::fill_fragment(acc[i][j], 0.f);

    // causal: rows in this block attend only to j <= i0+127
    const int KT = causal ? ((i0 >> 4) + 8) : (Sq >> 4);

#pragma unroll
    for (int c = t; c < 512; c += 256) {
        int row = c >> 2, sg = c & 3;
        cp16(&As[0][row][sg*4], Abw + (size_t)row * Sq + sg*4);
    }
    {
        int row = t >> 4, sg = t & 15;
        cp16(&Bs[0][row][sg*4], Bb + (size_t)row * Dm + sg*4);
    }
    CP_COMMIT();

    for (int kt = 0; kt < KT; kt++) {
        const int cur = kt & 1;
        if (kt + 1 < KT) {
            const int k0 = (kt + 1) << 4;
#pragma unroll
            for (int c = t; c < 512; c += 256) {
                int row = c >> 2, sg = c & 3;
                cp16(&As[cur^1][row][sg*4], Abw + (size_t)row * Sq + k0 + sg*4);
            }
            {
                int row = t >> 4, sg = t & 15;
                cp16(&Bs[cur^1][row][sg*4], Bb + (size_t)(k0 + row) * Dm + sg*4);
            }
            CP_COMMIT();
            CP_WAIT1();
        } else {
            CP_WAIT0();
        }
        __syncthreads();

        // normalize tile in SMEM and write final aw
        {
            int row = t >> 1, c0 = (t & 1) * 8;
            float inv = invs[row];
            float4 a0 = *(float4*)&As[cur][row][c0];
            float4 a1 = *(float4*)&As[cur][row][c0 + 4];
            a0.x *= inv; a0.y *= inv; a0.z *= inv; a0.w *= inv;
            a1.x *= inv; a1.y *= inv; a1.z *= inv; a1.w *= inv;
            *(float4*)&As[cur][row][c0]     = a0;
            *(float4*)&As[cur][row][c0 + 4] = a1;
            float* aww = Abw + (size_t)row * Sq + (kt << 4) + c0;
            *(float4*)aww       = a0;
            *(float4*)(aww + 4) = a1;
        }
        __syncthreads();

#pragma unroll
        for (int ks = 0; ks < 16; ks += 8) {
            wmma::fragment<wmma::matrix_a, 16, 16, 8, wmma::precision::tf32,
                           wmma::row_major> af[2];
            wmma::fragment<wmma::matrix_b, 16, 16, 8, wmma::precision::tf32,
                           wmma::row_major> bf[2];
#pragma unroll
            for (int i = 0; i < 2; i++)
                wmma::load_matrix_sync(af[i], &As[cur][wm + i*16][ks], 24);
#pragma unroll
            for (int j = 0; j < 2; j++)
                wmma::load_matrix_sync(bf[j], &Bs[cur][ks][wn + j*16], 72);
#pragma unroll
            for (int i = 0; i < 2; i++)
#pragma unroll
                for (int j = 0; j < 2; j++)
                    wmma::mma_sync(acc[i][j], af[i], bf[j], acc[i][j]);
        }
        __syncthreads();
    }

#pragma unroll
    for (int i = 0; i < 2; i++)
#pragma unroll
        for (int j = 0; j < 2; j++)
            wmma::store_matrix_sync(
                &Cb[(size_t)(i0 + wm + i*16) * Dm + wn + j*16],
                acc[i][j], Dm, wmma::mem_row_major);
}

// ---------------- residual add + layernorm over last dim (512) --------------
__global__ void __launch_bounds__(128) add_ln(
    const float* __restrict__ a, const float* __restrict__ r,
    const float* __restrict__ g, const float* __restrict__ be,
    float* __restrict__ out)
{
    const size_t row = blockIdx.x;
    const int t = threadIdx.x;
    __shared__ float red[4];

    float4 va = *(const float4*)&a[row * Dm + t*4];
    float4 vr = *(const float4*)&r[row * Dm + t*4];
    float x0 = va.x + vr.x, x1 = va.y + vr.y, x2 = va.z + vr.z, x3 = va.w + vr.w;

    float s = x0 + x1 + x2 + x3;
#pragma unroll
    for (int o = 16; o; o >>= 1) s += __shfl_xor_sync(0xffffffffu, s, o);
    if ((t & 31) == 0) red[t >> 5] = s;
    __syncthreads();
    float mean = (red[0] + red[1] + red[2] + red[3]) * (1.f / 512.f);

    float d0 = x0 - mean, d1 = x1 - mean, d2 = x2 - mean, d3 = x3 - mean;
    float vs = d0*d0 + d1*d1 + d2*d2 + d3*d3;
#pragma unroll
    for (int o = 16; o; o >>= 1) vs += __shfl_xor_sync(0xffffffffu, vs, o);
    __syncthreads();
    if ((t & 31) == 0) red[t >> 5] = vs;
    __syncthreads();
    float var = (red[0] + red[1] + red[2] + red[3]) * (1.f / 512.f);
    float rstd = rsqrtf(var + 1e-6f);

    float4 vg = *(const float4*)&g[t*4];
    float4 vb = *(const float4*)&be[t*4];
    float4 o4;
    o4.x = d0 * rstd * vg.x + vb.x;
    o4.y = d1 * rstd * vg.y + vb.y;
    o4.z = d2 * rstd * vg.z + vb.z;
    o4.w = d3 * rstd * vg.w + vb.w;
    *(float4*)&out[row * Dm + t*4] = o4;
}

// ---------------- launch ----------------------------------------------------
extern "C" void kernel_launch(void* const* d_in, const int* in_sizes, int n_in,
                              void* d_out, int out_size)
{
    const float* x    = (const float*)d_in[0];
    const float* enc  = (const float*)d_in[1];
    const float* wq1 = (const float*)d_in[3],  *bq1 = (const float*)d_in[4];
    const float* wk1 = (const float*)d_in[5],  *bk1 = (const float*)d_in[6];
    const float* wv1 = (const float*)d_in[7],  *bv1 = (const float*)d_in[8];
    const float* wo1 = (const float*)d_in[9],  *bo1 = (const float*)d_in[10];
    const float* wq2 = (const float*)d_in[11], *bq2 = (const float*)d_in[12];
    const float* wk2 = (const float*)d_in[13], *bk2 = (const float*)d_in[14];
    const float* wv2 = (const float*)d_in[15], *bv2 = (const float*)d_in[16];
    const float* wo2 = (const float*)d_in[17], *bo2 = (const float*)d_in[18];
    const float* wf1 = (const float*)d_in[19], *bf1 = (const float*)d_in[20];
    const float* wf2 = (const float*)d_in[21], *bf2 = (const float*)d_in[22];
    const float* g1 = (const float*)d_in[23], *be1 = (const float*)d_in[24];
    const float* g2 = (const float*)d_in[25], *be2 = (const float*)d_in[26];
    const float* g3 = (const float*)d_in[27], *be3 = (const float*)d_in[28];

    float* out3 = (float*)d_out;
    float* aw1  = out3 + (size_t)NB * Sq * Dm;
    float* aw2  = aw1  + (size_t)NB * NH * Sq * Sq;

    float *q, *k, *v, *t0, *o1, *o2, *ffh, *part;
    cudaGetSymbolAddress((void**)&q,   g_q);
    cudaGetSymbolAddress((void**)&k,   g_k);
    cudaGetSymbolAddress((void**)&v,   g_v);
    cudaGetSymbolAddress((void**)&t0,  g_t0);
    cudaGetSymbolAddress((void**)&o1,  g_o1);
    cudaGetSymbolAddress((void**)&o2,  g_o2);
    cudaGetSymbolAddress((void**)&ffh, g_ffh);
    cudaGetSymbolAddress((void**)&part, g_part);

    const int SMEM_GEMM = 50688;
    const int SMEM_LOG  = 69632;
    cudaFuncSetAttribute(wm_gemm<false>, cudaFuncAttributeMaxDynamicSharedMemorySize, SMEM_GEMM);
    cudaFuncSetAttribute(wm_gemm<true>,  cudaFuncAttributeMaxDynamicSharedMemorySize, SMEM_GEMM);
    cudaFuncSetAttribute(wm_gemm3,       cudaFuncAttributeMaxDynamicSharedMemorySize, SMEM_GEMM);
    cudaFuncSetAttribute(wm_logits_exp,  cudaFuncAttributeMaxDynamicSharedMemorySize, SMEM_LOG);

    const dim3 gProj64(Dm / 128, MROWS / 64);       // (4, 64)
    const dim3 gQKV(12, MROWS / 128);               // (12, 32)
    const dim3 gFF1(FFd / 128, MROWS / 128);        // (16, 32)
    const dim3 gLog(Sq / 128, Sq / 128, NB * NH);   // (16, 16, 16)
    const dim3 gAV(Sq / 128, NB * NH);              // (16, 16)

    // ---- self attention ----
    wm_gemm3<<<gQKV, 256, SMEM_GEMM>>>(x, x, x, wq1, wk1, wv1,
                                       bq1, bk1, bv1, q, k, v, Dm, Dm);
    wm_logits_exp<<<gLog, 256, SMEM_LOG>>>(q, k, aw1, part, 1);
    wm_av_norm<<<gAV, 256>>>(aw1, v, part, t0, 1);
    wm_gemm64<<<gProj64, 256>>>(t0, wo1, bo1, q, Dm, Dm);
    add_ln<<<MROWS, 128>>>(q, x, g1, be1, o1);

    // ---- cross attention ----
    wm_gemm3<<<gQKV, 256, SMEM_GEMM>>>(o1, enc, enc, wq2, wk2, wv2,
                                       bq2, bk2, bv2, q, k, v, Dm, Dm);
    wm_logits_exp<<<gLog, 256, SMEM_LOG>>>(q, k, aw2, part, 0);
    wm_av_norm<<<gAV, 256>>>(aw2, v, part, t0, 0);
    wm_gemm64<<<gProj64, 256>>>(t0, wo2, bo2, q, Dm, Dm);
    add_ln<<<MROWS, 128>>>(q, o1, g2, be2, o2);

    // ---- FFN ----
    wm_gemm<true ><<<gFF1, 256, SMEM_GEMM>>>(o2, wf1, bf1, ffh, FFd, Dm);
    wm_gemm64<<<gProj64, 256>>>(ffh, wf2, bf2, t0, Dm, FFd);
    add_ln<<<MROWS, 128>>>(t0, o2, g3, be3, out3);
}

// round 7
// speedup vs baseline: 2.0276x; 1.0008x over previous
#include <cuda_runtime.h>
#include <math.h>
#include <stdint.h>
#include <mma.h>

using namespace nvcuda;

// Problem constants
#define Sq   2048
#define Dm   512
#define NH   8
#define DKh  64
#define NB   2
#define FFd  2048
#define MROWS (NB*Sq)   // 4096

// ---------------- scratch (static device globals; no allocs) ----------------
__device__ float g_q  [MROWS*Dm];
__device__ float g_k  [MROWS*Dm];
__device__ float g_v  [MROWS*Dm];
__device__ float g_t0 [MROWS*Dm];
__device__ float g_o1 [MROWS*Dm];
__device__ float g_o2 [MROWS*Dm];
__device__ float g_ffh[MROWS*FFd];
__device__ float g_part[(size_t)NB*NH*Sq*16];   // row partial sums (2MB)

// ---------------- cp.async helpers ------------------------------------------
__device__ __forceinline__ void cp16(const void* dst, const void* src) {
    uint32_t d = (uint32_t)__cvta_generic_to_shared(dst);
    asm volatile("cp.async.cg.shared.global [%0], [%1], 16;" :: "r"(d), "l"(src));
}
#define CP_COMMIT() asm volatile("cp.async.commit_group;" ::: "memory")
#define CP_WAIT1()  asm volatile("cp.async.wait_group 1;" ::: "memory")
#define CP_WAIT0()  asm volatile("cp.async.wait_group 0;" ::: "memory")

// =============== shared GEMM body: C = A[.,K] @ B[K,N] + bias ================
// BM=128, BN=128, BK=16, 2-stage cp.async pipeline, 256 threads
__device__ __forceinline__ void gemm_body(
    const float* __restrict__ A, const float* __restrict__ B,
    const float* __restrict__ bias, float* __restrict__ C,
    int N, int K, int m0, int n0, bool relu, char* sm)
{
    float (*As)[128][24] = (float(*)[128][24])sm;                 // 2 x 12288
    float (*Bs)[16][136] = (float(*)[16][136])(sm + 24576);       // 2 x 8704
    float (*BiasS)[136]  = (float(*)[136])(sm + 41984);           // 8704

    const int t = threadIdx.x, wid = t >> 5;
    const int wm = (wid & 3) * 32, wn = (wid >> 2) * 64;

    {
        int col = t & 127, r0 = (t >> 7) * 8;
        float bv = bias[n0 + col];
#pragma unroll
        for (int r = 0; r < 8; r++) BiasS[r0 + r][col] = bv;
    }
    __syncthreads();

    wmma::fragment<wmma::accumulator, 16, 16, 8, float> acc[2][4];
#pragma unroll
    for (int i = 0; i < 2; i++)
#pragma unroll
        for (int j = 0; j < 4; j++)
            wmma::load_matrix_sync(acc[i][j], &BiasS[0][wn + j*16], 136,
                                   wmma::mem_row_major);

    const float* Ab = A + (size_t)m0 * K;
    const float* Bb = B + n0;

#pragma unroll
    for (int c = t; c < 512; c += 256) {
        int row = c >> 2, sg = c & 3;
        cp16(&As[0][row][sg*4], Ab + (size_t)row * K + sg*4);
    }
#pragma unroll
    for (int c = t; c < 512; c += 256) {
        int row = c >> 5, sg = c & 31;
        cp16(&Bs[0][row][sg*4], Bb + (size_t)row * N + sg*4);
    }
    CP_COMMIT();

    const int KT = K >> 4;
    for (int kt = 0; kt < KT; kt++) {
        const int cur = kt & 1;
        if (kt + 1 < KT) {
            const int k0 = (kt + 1) << 4;
#pragma unroll
            for (int c = t; c < 512; c += 256) {
                int row = c >> 2, sg = c & 3;
                cp16(&As[cur^1][row][sg*4], Ab + (size_t)row * K + k0 + sg*4);
            }
#pragma unroll
            for (int c = t; c < 512; c += 256) {
                int row = c >> 5, sg = c & 31;
                cp16(&Bs[cur^1][row][sg*4], Bb + (size_t)(k0 + row) * N + sg*4);
            }
            CP_COMMIT();
            CP_WAIT1();
        } else {
            CP_WAIT0();
        }
        __syncthreads();
#pragma unroll
        for (int ks = 0; ks < 16; ks += 8) {
            wmma::fragment<wmma::matrix_a, 16, 16, 8, wmma::precision::tf32,
                           wmma::row_major> af[2];
            wmma::fragment<wmma::matrix_b, 16, 16, 8, wmma::precision::tf32,
                           wmma::row_major> bf[4];
#pragma unroll
            for (int i = 0; i < 2; i++)
                wmma::load_matrix_sync(af[i], &As[cur][wm + i*16][ks], 24);
#pragma unroll
            for (int j = 0; j < 4; j++)
                wmma::load_matrix_sync(bf[j], &Bs[cur][ks][wn + j*16], 136);
#pragma unroll
            for (int i = 0; i < 2; i++)
#pragma unroll
                for (int j = 0; j < 4; j++)
                    wmma::mma_sync(acc[i][j], af[i], bf[j], acc[i][j]);
        }
        __syncthreads();
    }

#pragma unroll
    for (int i = 0; i < 2; i++)
#pragma unroll
        for (int j = 0; j < 4; j++) {
            if (relu) {
#pragma unroll
                for (int e = 0; e < acc[i][j].num_elements; e++)
                    acc[i][j].x[e] = fmaxf(acc[i][j].x[e], 0.f);
            }
            wmma::store_matrix_sync(
                &C[(size_t)(m0 + wm + i*16) * N + n0 + wn + j*16],
                acc[i][j], N, wmma::mem_row_major);
        }
}

template<bool RELU>
__global__ void __launch_bounds__(256, 2) wm_gemm(
    const float* __restrict__ A, const float* __restrict__ B,
    const float* __restrict__ bias, float* __restrict__ C, int N, int K)
{
    extern __shared__ char sm[];
    gemm_body(A, B, bias, C, N, K, blockIdx.y * 128, blockIdx.x * 128, RELU, sm);
}

// fused triple GEMM (shares grid across 3 weight matrices, N=512 each)
__global__ void __launch_bounds__(256, 2) wm_gemm3(
    const float* __restrict__ A0, const float* __restrict__ A1,
    const float* __restrict__ A2,
    const float* __restrict__ B0, const float* __restrict__ B1,
    const float* __restrict__ B2,
    const float* __restrict__ b0, const float* __restrict__ b1,
    const float* __restrict__ b2,
    float* __restrict__ C0, float* __restrict__ C1, float* __restrict__ C2,
    int N, int K)
{
    extern __shared__ char sm[];
    const int mat = blockIdx.x >> 2;
    const float* A = (mat == 0) ? A0 : (mat == 1) ? A1 : A2;
    const float* B = (mat == 0) ? B0 : (mat == 1) ? B1 : B2;
    const float* bias = (mat == 0) ? b0 : (mat == 1) ? b1 : b2;
    float* C = (mat == 0) ? C0 : (mat == 1) ? C1 : C2;
    gemm_body(A, B, bias, C, N, K, blockIdx.y * 128, (blockIdx.x & 3) * 128,
              false, sm);
}

// =============== BM=64 GEMM for underfilled shapes (wo, ff2) ================
__global__ void __launch_bounds__(256, 2) wm_gemm64(
    const float* __restrict__ A, const float* __restrict__ B,
    const float* __restrict__ bias, float* __restrict__ C, int N, int K)
{
    __shared__ float As[2][64][24];     // 12288
    __shared__ float Bs[2][16][136];    // 17408
    __shared__ float BiasS[16][136];    // 8704

    const int t = threadIdx.x, wid = t >> 5;
    const int m0 = blockIdx.y * 64, n0 = blockIdx.x * 128;
    const int wm = (wid & 3) * 16, wn = (wid >> 2) * 64;

    {
        int col = t & 127, r0 = (t >> 7) * 8;
        float bv = bias[n0 + col];
#pragma unroll
        for (int r = 0; r < 8; r++) BiasS[r0 + r][col] = bv;
    }
    __syncthreads();

    wmma::fragment<wmma::accumulator, 16, 16, 8, float> acc[4];
#pragma unroll
    for (int j = 0; j < 4; j++)
        wmma::load_matrix_sync(acc[j], &BiasS[0][wn + j*16], 136,
                               wmma::mem_row_major);

    const float* Ab = A + (size_t)m0 * K;
    const float* Bb = B + n0;

    {
        int row = t >> 2, sg = t & 3;
        cp16(&As[0][row][sg*4], Ab + (size_t)row * K + sg*4);
    }
#pragma unroll
    for (int c = t; c < 512; c += 256) {
        int row = c >> 5, sg = c & 31;
        cp16(&Bs[0][row][sg*4], Bb + (size_t)row * N + sg*4);
    }
    CP_COMMIT();

    const int KT = K >> 4;
    for (int kt = 0; kt < KT; kt++) {
        const int cur = kt & 1;
        if (kt + 1 < KT) {
            const int k0 = (kt + 1) << 4;
            {
                int row = t >> 2, sg = t & 3;
                cp16(&As[cur^1][row][sg*4], Ab + (size_t)row * K + k0 + sg*4);
            }
#pragma unroll
            for (int c = t; c < 512; c += 256) {
                int row = c >> 5, sg = c & 31;
                cp16(&Bs[cur^1][row][sg*4], Bb + (size_t)(k0 + row) * N + sg*4);
            }
            CP_COMMIT();
            CP_WAIT1();
        } else {
            CP_WAIT0();
        }
        __syncthreads();
#pragma unroll
        for (int ks = 0; ks < 16; ks += 8) {
            wmma::fragment<wmma::matrix_a, 16, 16, 8, wmma::precision::tf32,
                           wmma::row_major> af;
            wmma::fragment<wmma::matrix_b, 16, 16, 8, wmma::precision::tf32,
                           wmma::row_major> bf[4];
            wmma::load_matrix_sync(af, &As[cur][wm][ks], 24);
#pragma unroll
            for (int j = 0; j < 4; j++)
                wmma::load_matrix_sync(bf[j], &Bs[cur][ks][wn + j*16], 136);
#pragma unroll
            for (int j = 0; j < 4; j++)
                wmma::mma_sync(acc[j], af, bf[j], acc[j]);
        }
        __syncthreads();
    }

#pragma unroll
    for (int j = 0; j < 4; j++)
        wmma::store_matrix_sync(&C[(size_t)(m0 + wm) * N + n0 + wn + j*16],
                                acc[j], N, wmma::mem_row_major);
}

// ===== logits+exp: E = exp(scale*Q@K^T) (masked->0) + row partial sums ======
__global__ void __launch_bounds__(256, 2) wm_logits_exp(
    const float* __restrict__ Q, const float* __restrict__ Km,
    float* __restrict__ out, float* __restrict__ part, int causal)
{
    extern __shared__ char smc[];
    float (*Qs)[68] = (float(*)[68])smc;                 // 34816
    float (*Ks)[68] = (float(*)[68])(smc + 34816);       // 34816
    float (*St)[136] = (float(*)[136])smc;               // reuse: 69632

    const int bh = blockIdx.z;
    const int b = bh >> 3, h = bh & 7;
    const int i0 = blockIdx.y * 128, j0 = blockIdx.x * 128;
    const int jt = blockIdx.x;
    const int t = threadIdx.x, wid = t >> 5;
    float* Ob = out + (size_t)bh * Sq * Sq;

    if (causal && j0 > i0 + 127) {
        // fully masked: E = 0 (this is also the final aw value here)
        const float4 zero = make_float4(0.f, 0.f, 0.f, 0.f);
        for (int idx = t; idx < 4096; idx += 256) {
            int row = idx >> 5, c4 = idx & 31;
            *(float4*)&Ob[(size_t)(i0 + row) * Sq + j0 + c4 * 4] = zero;
        }
        if (t < 128)
            part[((size_t)bh * Sq + i0 + t) * 16 + jt] = 0.f;
        return;
    }

    const float* Qb = Q  + (size_t)b * Sq * Dm + h * DKh + (size_t)i0 * Dm;
    const float* Kb = Km + (size_t)b * Sq * Dm + h * DKh + (size_t)j0 * Dm;

#pragma unroll
    for (int c = t; c < 2048; c += 256) {
        int row = c >> 4, sg = c & 15;
        cp16(&Qs[row][sg*4], Qb + (size_t)row * Dm + sg*4);
    }
#pragma unroll
    for (int c = t; c < 2048; c += 256) {
        int row = c >> 4, sg = c & 15;
        cp16(&Ks[row][sg*4], Kb + (size_t)row * Dm + sg*4);
    }
    CP_COMMIT();
    CP_WAIT0();
    __syncthreads();

    const int wm = (wid & 3) * 32, wn = (wid >> 2) * 64;
    wmma::fragment<wmma::accumulator, 16, 16, 8, float> acc[2][4];
#pragma unroll
    for (int i = 0; i < 2; i++)
#pragma unroll
        for (int j = 0; j < 4; j++) wmma::fill_fragment(acc[i][j], 0.f);

#pragma unroll
    for (int ks = 0; ks < 64; ks += 8) {
        wmma::fragment<wmma::matrix_a, 16, 16, 8, wmma::precision::tf32,
                       wmma::row_major> af[2];
        wmma::fragment<wmma::matrix_b, 16, 16, 8, wmma::precision::tf32,
                       wmma::col_major> bf[4];
#pragma unroll
        for (int i = 0; i < 2; i++)
            wmma::load_matrix_sync(af[i], &Qs[wm + i*16][ks], 68);
#pragma unroll
        for (int j = 0; j < 4; j++)
            wmma::load_matrix_sync(bf[j], &Ks[wn + j*16][ks], 68);
#pragma unroll
        for (int i = 0; i < 2; i++)
#pragma unroll
            for (int j = 0; j < 4; j++)
                wmma::mma_sync(acc[i][j], af[i], bf[j], acc[i][j]);
    }
    __syncthreads();   // done with Qs/Ks; reuse as staging

#pragma unroll
    for (int i = 0; i < 2; i++)
#pragma unroll
        for (int j = 0; j < 4; j++)
            wmma::store_matrix_sync(&St[wm + i*16][wn + j*16], acc[i][j], 136,
                                    wmma::mem_row_major);
    __syncthreads();

    // epilogue: E = exp(s/8) with causal zeros, plus per-row partial sum
    {
        int row = t >> 1, cb = (t & 1) * 64;
        int gi = i0 + row;
        float* orow = Ob + (size_t)gi * Sq + j0 + cb;
        float psum = 0.f;
#pragma unroll
        for (int u = 0; u < 16; u++) {
            float4 v;
            int gj = j0 + cb + u * 4;
            v.x = (causal && gj+0 > gi) ? 0.f : __expf(St[row][cb + u*4 + 0] * 0.125f);
            v.y = (causal && gj+1 > gi) ? 0.f : __expf(St[row][cb + u*4 + 1] * 0.125f);
            v.z = (causal && gj+2 > gi) ? 0.f : __expf(St[row][cb + u*4 + 2] * 0.125f);
            v.w = (causal && gj+3 > gi) ? 0.f : __expf(St[row][cb + u*4 + 3] * 0.125f);
            psum += v.x + v.y + v.z + v.w;
            *(float4*)(orow + u * 4) = v;
        }
        psum += __shfl_xor_sync(0xffffffffu, psum, 1);
        if ((t & 1) == 0)
            part[((size_t)bh * Sq + gi) * 16 + jt] = psum;
    }
}

// ===== AV with fused normalize: reads E, writes aw = E/sum and out = aw@V ===
__global__ void __launch_bounds__(256, 2) wm_av_norm(
    float* __restrict__ aw, const float* __restrict__ V,
    const float* __restrict__ part, float* __restrict__ out, int causal)
{
    __shared__ float As[2][128][24];   // 24576
    __shared__ float Bs[2][16][72];    // 9216
    __shared__ float invs[128];

    const int bh = blockIdx.y;
    const int b = bh >> 3, h = bh & 7;
    const int i0 = blockIdx.x * 128;
    const int t = threadIdx.x, wid = t >> 5;

    float*       Abw = aw + (size_t)bh * Sq * Sq + (size_t)i0 * Sq;
    const float* Bb  = V + (size_t)b * Sq * Dm + h * DKh;
    float*       Cb  = out + (size_t)b * Sq * Dm + h * DKh;

    // per-row inverse softmax sums (deterministic partial reduction)
    if (t < 128) {
        const float* pp = part + ((size_t)bh * Sq + i0 + t) * 16;
        float s = 0.f;
#pragma unroll
        for (int jt = 0; jt < 16; jt++) s += pp[jt];
        invs[t] = 1.f / s;
    }

    const int wm = (wid & 3) * 32, wn = (wid >> 2) * 32;
    wmma::fragment<wmma::accumulator, 16, 16, 8, float> acc[2][2];
#pragma unroll
    for (int i = 0; i < 2; i++)
#pragma unroll
        for (int j = 0; j < 2; j++) wmma::fill_fragment(acc[i][j], 0.f);

    // causal: rows in this block attend only to j <= i0+127
    const int KT = causal ? ((i0 >> 4) + 8) : (Sq >> 4);

#pragma unroll
    for (int c = t; c < 512; c += 256) {
        int row = c >> 2, sg = c & 3;
        cp16(&As[0][row][sg*4], Abw + (size_t)row * Sq + sg*4);
    }
    {
        int row = t >> 4, sg = t & 15;
        cp16(&Bs[0][row][sg*4], Bb + (size_t)row * Dm + sg*4);
    }
    CP_COMMIT();

    for (int kt = 0; kt < KT; kt++) {
        const int cur = kt & 1;
        if (kt + 1 < KT) {
            const int k0 = (kt + 1) << 4;
#pragma unroll
            for (int c = t; c < 512; c += 256) {
                int row = c >> 2, sg = c & 3;
                cp16(&As[cur^1][row][sg*4], Abw + (size_t)row * Sq + k0 + sg*4);
            }
            {
                int row = t >> 4, sg = t & 15;
                cp16(&Bs[cur^1][row][sg*4], Bb + (size_t)(k0 + row) * Dm + sg*4);
            }
            CP_COMMIT();
            CP_WAIT1();
        } else {
            CP_WAIT0();
        }
        __syncthreads();

        // normalize tile in SMEM and write final aw
        {
            int row = t >> 1, c0 = (t & 1) * 8;
            float inv = invs[row];
            float4 a0 = *(float4*)&As[cur][row][c0];
            float4 a1 = *(float4*)&As[cur][row][c0 + 4];
            a0.x *= inv; a0.y *= inv; a0.z *= inv; a0.w *= inv;
            a1.x *= inv; a1.y *= inv; a1.z *= inv; a1.w *= inv;
            *(float4*)&As[cur][row][c0]     = a0;
            *(float4*)&As[cur][row][c0 + 4] = a1;
            float* aww = Abw + (size_t)row * Sq + (kt << 4) + c0;
            *(float4*)aww       = a0;
            *(float4*)(aww + 4) = a1;
        }
        __syncthreads();

#pragma unroll
        for (int ks = 0; ks < 16; ks += 8) {
            wmma::fragment<wmma::matrix_a, 16, 16, 8, wmma::precision::tf32,
                           wmma::row_major> af[2];
            wmma::fragment<wmma::matrix_b, 16, 16, 8, wmma::precision::tf32,
                           wmma::row_major> bf[2];
#pragma unroll
            for (int i = 0; i < 2; i++)
                wmma::load_matrix_sync(af[i], &As[cur][wm + i*16][ks], 24);
#pragma unroll
            for (int j = 0; j < 2; j++)
                wmma::load_matrix_sync(bf[j], &Bs[cur][ks][wn + j*16], 72);
#pragma unroll
            for (int i = 0; i < 2; i++)
#pragma unroll
                for (int j = 0; j < 2; j++)
                    wmma::mma_sync(acc[i][j], af[i], bf[j], acc[i][j]);
        }
        __syncthreads();
    }

#pragma unroll
    for (int i = 0; i < 2; i++)
#pragma unroll
        for (int j = 0; j < 2; j++)
            wmma::store_matrix_sync(
                &Cb[(size_t)(i0 + wm + i*16) * Dm + wn + j*16],
                acc[i][j], Dm, wmma::mem_row_major);
}

// ---------------- residual add + layernorm over last dim (512) --------------
__global__ void __launch_bounds__(128) add_ln(
    const float* __restrict__ a, const float* __restrict__ r,
    const float* __restrict__ g, const float* __restrict__ be,
    float* __restrict__ out)
{
    const size_t row = blockIdx.x;
    const int t = threadIdx.x;
    __shared__ float red[4];

    float4 va = *(const float4*)&a[row * Dm + t*4];
    float4 vr = *(const float4*)&r[row * Dm + t*4];
    float x0 = va.x + vr.x, x1 = va.y + vr.y, x2 = va.z + vr.z, x3 = va.w + vr.w;

    float s = x0 + x1 + x2 + x3;
#pragma unroll
    for (int o = 16; o; o >>= 1) s += __shfl_xor_sync(0xffffffffu, s, o);
    if ((t & 31) == 0) red[t >> 5] = s;
    __syncthreads();
    float mean = (red[0] + red[1] + red[2] + red[3]) * (1.f / 512.f);

    float d0 = x0 - mean, d1 = x1 - mean, d2 = x2 - mean, d3 = x3 - mean;
    float vs = d0*d0 + d1*d1 + d2*d2 + d3*d3;
#pragma unroll
    for (int o = 16; o; o >>= 1) vs += __shfl_xor_sync(0xffffffffu, vs, o);
    __syncthreads();
    if ((t & 31) == 0) red[t >> 5] = vs;
    __syncthreads();
    float var = (red[0] + red[1] + red[2] + red[3]) * (1.f / 512.f);
    float rstd = rsqrtf(var + 1e-6f);

    float4 vg = *(const float4*)&g[t*4];
    float4 vb = *(const float4*)&be[t*4];
    float4 o4;
    o4.x = d0 * rstd * vg.x + vb.x;
    o4.y = d1 * rstd * vg.y + vb.y;
    o4.z = d2 * rstd * vg.z + vb.z;
    o4.w = d3 * rstd * vg.w + vb.w;
    *(float4*)&out[row * Dm + t*4] = o4;
}

// ---------------- launch ----------------------------------------------------
extern "C" void kernel_launch(void* const* d_in, const int* in_sizes, int n_in,
                              void* d_out, int out_size)
{
    const float* x    = (const float*)d_in[0];
    const float* enc  = (const float*)d_in[1];
    const float* wq1 = (const float*)d_in[3],  *bq1 = (const float*)d_in[4];
    const float* wk1 = (const float*)d_in[5],  *bk1 = (const float*)d_in[6];
    const float* wv1 = (const float*)d_in[7],  *bv1 = (const float*)d_in[8];
    const float* wo1 = (const float*)d_in[9],  *bo1 = (const float*)d_in[10];
    const float* wq2 = (const float*)d_in[11], *bq2 = (const float*)d_in[12];
    const float* wk2 = (const float*)d_in[13], *bk2 = (const float*)d_in[14];
    const float* wv2 = (const float*)d_in[15], *bv2 = (const float*)d_in[16];
    const float* wo2 = (const float*)d_in[17], *bo2 = (const float*)d_in[18];
    const float* wf1 = (const float*)d_in[19], *bf1 = (const float*)d_in[20];
    const float* wf2 = (const float*)d_in[21], *bf2 = (const float*)d_in[22];
    const float* g1 = (const float*)d_in[23], *be1 = (const float*)d_in[24];
    const float* g2 = (const float*)d_in[25], *be2 = (const float*)d_in[26];
    const float* g3 = (const float*)d_in[27], *be3 = (const float*)d_in[28];

    float* out3 = (float*)d_out;
    float* aw1  = out3 + (size_t)NB * Sq * Dm;
    float* aw2  = aw1  + (size_t)NB * NH * Sq * Sq;

    float *q, *k, *v, *t0, *o1, *o2, *ffh, *part;
    cudaGetSymbolAddress((void**)&q,   g_q);
    cudaGetSymbolAddress((void**)&k,   g_k);
    cudaGetSymbolAddress((void**)&v,   g_v);
    cudaGetSymbolAddress((void**)&t0,  g_t0);
    cudaGetSymbolAddress((void**)&o1,  g_o1);
    cudaGetSymbolAddress((void**)&o2,  g_o2);
    cudaGetSymbolAddress((void**)&ffh, g_ffh);
    cudaGetSymbolAddress((void**)&part, g_part);

    const int SMEM_GEMM = 50688;
    const int SMEM_LOG  = 69632;
    cudaFuncSetAttribute(wm_gemm<false>, cudaFuncAttributeMaxDynamicSharedMemorySize, SMEM_GEMM);
    cudaFuncSetAttribute(wm_gemm<true>,  cudaFuncAttributeMaxDynamicSharedMemorySize, SMEM_GEMM);
    cudaFuncSetAttribute(wm_gemm3,       cudaFuncAttributeMaxDynamicSharedMemorySize, SMEM_GEMM);
    cudaFuncSetAttribute(wm_logits_exp,  cudaFuncAttributeMaxDynamicSharedMemorySize, SMEM_LOG);

    const dim3 gProj64(Dm / 128, MROWS / 64);       // (4, 64)
    const dim3 gQKV(12, MROWS / 128);               // (12, 32)
    const dim3 gFF1(FFd / 128, MROWS / 128);        // (16, 32)
    const dim3 gLog(Sq / 128, Sq / 128, NB * NH);   // (16, 16, 16)
    const dim3 gAV(Sq / 128, NB * NH);              // (16, 16)

    // ---- self attention ----
    wm_gemm3<<<gQKV, 256, SMEM_GEMM>>>(x, x, x, wq1, wk1, wv1,
                                       bq1, bk1, bv1, q, k, v, Dm, Dm);
    wm_logits_exp<<<gLog, 256, SMEM_LOG>>>(q, k, aw1, part, 1);
    wm_av_norm<<<gAV, 256>>>(aw1, v, part, t0, 1);
    wm_gemm64<<<gProj64, 256>>>(t0, wo1, bo1, q, Dm, Dm);
    add_ln<<<MROWS, 128>>>(q, x, g1, be1, o1);

    // ---- cross attention ----
    wm_gemm3<<<gQKV, 256, SMEM_GEMM>>>(o1, enc, enc, wq2, wk2, wv2,
                                       bq2, bk2, bv2, q, k, v, Dm, Dm);
    wm_logits_exp<<<gLog, 256, SMEM_LOG>>>(q, k, aw2, part, 0);
    wm_av_norm<<<gAV, 256>>>(aw2, v, part, t0, 0);
    wm_gemm64<<<gProj64, 256>>>(t0, wo2, bo2, q, Dm, Dm);
    add_ln<<<MROWS, 128>>>(q, o1, g2, be2, o2);

    // ---- FFN ----
    wm_gemm<true ><<<gFF1, 256, SMEM_GEMM>>>(o2, wf1, bf1, ffh, FFd, Dm);
    wm_gemm64<<<gProj64, 256>>>(ffh, wf2, bf2, t0, Dm, FFd);
    add_ln<<<MROWS, 128>>>(t0, o2, g3, be3, out3);
}

// round 8
// speedup vs baseline: 2.1758x; 1.0731x over previous
#include <cuda_runtime.h>
#include <math.h>
#include <stdint.h>
#include <mma.h>

using namespace nvcuda;

// Problem constants
#define Sq   2048
#define Dm   512
#define NH   8
#define DKh  64
#define NB   2
#define FFd  2048
#define MROWS (NB*Sq)   // 4096

// ---------------- scratch (static device globals; no allocs) ----------------
__device__ float g_q  [MROWS*Dm];
__device__ float g_k  [MROWS*Dm];
__device__ float g_v  [MROWS*Dm];
__device__ float g_t0 [MROWS*Dm];
__device__ float g_t0b[MROWS*Dm];
__device__ float g_o1 [MROWS*Dm];
__device__ float g_o2 [MROWS*Dm];
__device__ float g_ffh[MROWS*FFd];
__device__ float g_part[(size_t)NB*NH*Sq*16];   // row partial sums (2MB)

// ---------------- cp.async helpers ------------------------------------------
__device__ __forceinline__ void cp16(const void* dst, const void* src) {
    uint32_t d = (uint32_t)__cvta_generic_to_shared(dst);
    asm volatile("cp.async.cg.shared.global [%0], [%1], 16;" :: "r"(d), "l"(src));
}
#define CP_COMMIT() asm volatile("cp.async.commit_group;" ::: "memory")
#define CP_WAIT1()  asm volatile("cp.async.wait_group 1;" ::: "memory")
#define CP_WAIT0()  asm volatile("cp.async.wait_group 0;" ::: "memory")

// =============== shared GEMM body: C = A[.,K] @ B[K,N] + bias ================
// BM=128, BN=128, BK=16, 3-stage cp.async, ONE sync per K-iter, 256 threads
__device__ __forceinline__ void gemm_body(
    const float* __restrict__ A, const float* __restrict__ B,
    const float* __restrict__ bias, float* __restrict__ C,
    int N, int K, int m0, int n0, bool relu, char* sm)
{
    float (*As)[128][24] = (float(*)[128][24])sm;                 // 3 x 12288
    float (*Bs)[16][136] = (float(*)[16][136])(sm + 36864);       // 3 x 8704
    float (*BiasS)[136]  = (float(*)[136])(sm + 62976);           // 8704

    const int t = threadIdx.x, wid = t >> 5;
    const int wm = (wid & 3) * 32, wn = (wid >> 2) * 64;

    {
        int col = t & 127, r0 = (t >> 7) * 8;
        float bv = bias[n0 + col];
#pragma unroll
        for (int r = 0; r < 8; r++) BiasS[r0 + r][col] = bv;
    }
    __syncthreads();

    wmma::fragment<wmma::accumulator, 16, 16, 8, float> acc[2][4];
#pragma unroll
    for (int i = 0; i < 2; i++)
#pragma unroll
        for (int j = 0; j < 4; j++)
            wmma::load_matrix_sync(acc[i][j], &BiasS[0][wn + j*16], 136,
                                   wmma::mem_row_major);

    const float* Ab = A + (size_t)m0 * K;
    const float* Bb = B + n0;

#define G_LOAD(st, k0)                                                    \
    {                                                                     \
        _Pragma("unroll")                                                 \
        for (int c = t; c < 512; c += 256) {                              \
            int row = c >> 2, sg = c & 3;                                 \
            cp16(&As[st][row][sg*4], Ab + (size_t)row * K + (k0) + sg*4); \
        }                                                                 \
        _Pragma("unroll")                                                 \
        for (int c = t; c < 512; c += 256) {                              \
            int row = c >> 5, sg = c & 31;                                \
            cp16(&Bs[st][row][sg*4], Bb + (size_t)((k0) + row) * N + sg*4); \
        }                                                                 \
        CP_COMMIT();                                                      \
    }

    G_LOAD(0, 0)
    G_LOAD(1, 16)

    const int KT = K >> 4;
    for (int kt = 0; kt < KT; kt++) {
        const int cur = kt % 3;
        if (kt + 1 < KT) CP_WAIT1(); else CP_WAIT0();
        __syncthreads();
        if (kt + 2 < KT) { int st = (kt + 2) % 3; G_LOAD(st, (kt + 2) << 4) }
#pragma unroll
        for (int ks = 0; ks < 16; ks += 8) {
            wmma::fragment<wmma::matrix_a, 16, 16, 8, wmma::precision::tf32,
                           wmma::row_major> af[2];
            wmma::fragment<wmma::matrix_b, 16, 16, 8, wmma::precision::tf32,
                           wmma::row_major> bf[4];
#pragma unroll
            for (int i = 0; i < 2; i++)
                wmma::load_matrix_sync(af[i], &As[cur][wm + i*16][ks], 24);
#pragma unroll
            for (int j = 0; j < 4; j++)
                wmma::load_matrix_sync(bf[j], &Bs[cur][ks][wn + j*16], 136);
#pragma unroll
            for (int i = 0; i < 2; i++)
#pragma unroll
                for (int j = 0; j < 4; j++)
                    wmma::mma_sync(acc[i][j], af[i], bf[j], acc[i][j]);
        }
    }
#undef G_LOAD

#pragma unroll
    for (int i = 0; i < 2; i++)
#pragma unroll
        for (int j = 0; j < 4; j++) {
            if (relu) {
#pragma unroll
                for (int e = 0; e < acc[i][j].num_elements; e++)
                    acc[i][j].x[e] = fmaxf(acc[i][j].x[e], 0.f);
            }
            wmma::store_matrix_sync(
                &C[(size_t)(m0 + wm + i*16) * N + n0 + wn + j*16],
                acc[i][j], N, wmma::mem_row_major);
        }
}

template<bool RELU>
__global__ void __launch_bounds__(256, 2) wm_gemm(
    const float* __restrict__ A, const float* __restrict__ B,
    const float* __restrict__ bias, float* __restrict__ C, int N, int K)
{
    extern __shared__ char sm[];
    gemm_body(A, B, bias, C, N, K, blockIdx.y * 128, blockIdx.x * 128, RELU, sm);
}

// fused triple GEMM (shares grid across 3 weight matrices, N=512 each)
__global__ void __launch_bounds__(256, 2) wm_gemm3(
    const float* __restrict__ A0, const float* __restrict__ A1,
    const float* __restrict__ A2,
    const float* __restrict__ B0, const float* __restrict__ B1,
    const float* __restrict__ B2,
    const float* __restrict__ b0, const float* __restrict__ b1,
    const float* __restrict__ b2,
    float* __restrict__ C0, float* __restrict__ C1, float* __restrict__ C2,
    int N, int K)
{
    extern __shared__ char sm[];
    const int mat = blockIdx.x >> 2;
    const float* A = (mat == 0) ? A0 : (mat == 1) ? A1 : A2;
    const float* B = (mat == 0) ? B0 : (mat == 1) ? B1 : B2;
    const float* bias = (mat == 0) ? b0 : (mat == 1) ? b1 : b2;
    float* C = (mat == 0) ? C0 : (mat == 1) ? C1 : C2;
    gemm_body(A, B, bias, C, N, K, blockIdx.y * 128, (blockIdx.x & 3) * 128,
              false, sm);
}

// =============== BM=64 GEMM for underfilled shapes (wo, ff2) ================
__global__ void __launch_bounds__(256, 2) wm_gemm64(
    const float* __restrict__ A, const float* __restrict__ B,
    const float* __restrict__ bias, float* __restrict__ C, int N, int K)
{
    extern __shared__ char sm[];
    float (*As)[64][24]  = (float(*)[64][24])sm;                  // 3 x 6144
    float (*Bs)[16][136] = (float(*)[16][136])(sm + 18432);       // 3 x 8704
    float (*BiasS)[136]  = (float(*)[136])(sm + 44544);           // 8704

    const int t = threadIdx.x, wid = t >> 5;
    const int m0 = blockIdx.y * 64, n0 = blockIdx.x * 128;
    const int wm = (wid & 3) * 16, wn = (wid >> 2) * 64;

    {
        int col = t & 127, r0 = (t >> 7) * 8;
        float bv = bias[n0 + col];
#pragma unroll
        for (int r = 0; r < 8; r++) BiasS[r0 + r][col] = bv;
    }
    __syncthreads();

    wmma::fragment<wmma::accumulator, 16, 16, 8, float> acc[4];
#pragma unroll
    for (int j = 0; j < 4; j++)
        wmma::load_matrix_sync(acc[j], &BiasS[0][wn + j*16], 136,
                               wmma::mem_row_major);

    const float* Ab = A + (size_t)m0 * K;
    const float* Bb = B + n0;

#define G64_LOAD(st, k0)                                                  \
    {                                                                     \
        int row = t >> 2, sg = t & 3;                                     \
        cp16(&As[st][row][sg*4], Ab + (size_t)row * K + (k0) + sg*4);     \
        _Pragma("unroll")                                                 \
        for (int c = t; c < 512; c += 256) {                              \
            int r2 = c >> 5, s2 = c & 31;                                 \
            cp16(&Bs[st][r2][s2*4], Bb + (size_t)((k0) + r2) * N + s2*4); \
        }                                                                 \
        CP_COMMIT();                                                      \
    }

    G64_LOAD(0, 0)
    G64_LOAD(1, 16)

    const int KT = K >> 4;
    for (int kt = 0; kt < KT; kt++) {
        const int cur = kt % 3;
        if (kt + 1 < KT) CP_WAIT1(); else CP_WAIT0();
        __syncthreads();
        if (kt + 2 < KT) { int st = (kt + 2) % 3; G64_LOAD(st, (kt + 2) << 4) }
#pragma unroll
        for (int ks = 0; ks < 16; ks += 8) {
            wmma::fragment<wmma::matrix_a, 16, 16, 8, wmma::precision::tf32,
                           wmma::row_major> af;
            wmma::fragment<wmma::matrix_b, 16, 16, 8, wmma::precision::tf32,
                           wmma::row_major> bf[4];
            wmma::load_matrix_sync(af, &As[cur][wm][ks], 24);
#pragma unroll
            for (int j = 0; j < 4; j++)
                wmma::load_matrix_sync(bf[j], &Bs[cur][ks][wn + j*16], 136);
#pragma unroll
            for (int j = 0; j < 4; j++)
                wmma::mma_sync(acc[j], af, bf[j], acc[j]);
        }
    }
#undef G64_LOAD

#pragma unroll
    for (int j = 0; j < 4; j++)
        wmma::store_matrix_sync(&C[(size_t)(m0 + wm) * N + n0 + wn + j*16],
                                acc[j], N, wmma::mem_row_major);
}

// ===== logits+exp: E = exp(scale*Q@K^T) (masked->0) + row partial sums ======
__global__ void __launch_bounds__(256, 2) wm_logits_exp(
    const float* __restrict__ Q, const float* __restrict__ Km,
    float* __restrict__ out, float* __restrict__ part, int causal)
{
    extern __shared__ char smc[];
    float (*Qs)[68] = (float(*)[68])smc;                 // 34816
    float (*Ks)[68] = (float(*)[68])(smc + 34816);       // 34816
    float (*St)[136] = (float(*)[136])smc;               // reuse: 69632

    const int bh = blockIdx.z;
    const int b = bh >> 3, h = bh & 7;
    const int i0 = blockIdx.y * 128, j0 = blockIdx.x * 128;
    const int jt = blockIdx.x;
    const int t = threadIdx.x, wid = t >> 5, lane = t & 31;
    float* Ob = out + (size_t)bh * Sq * Sq;

    if (causal && j0 > i0 + 127) {
        const float4 zero = make_float4(0.f, 0.f, 0.f, 0.f);
        for (int idx = t; idx < 4096; idx += 256) {
            int row = idx >> 5, c4 = idx & 31;
            *(float4*)&Ob[(size_t)(i0 + row) * Sq + j0 + c4 * 4] = zero;
        }
        if (t < 128)
            part[((size_t)bh * Sq + i0 + t) * 16 + jt] = 0.f;
        return;
    }

    const float* Qb = Q  + (size_t)b * Sq * Dm + h * DKh + (size_t)i0 * Dm;
    const float* Kb = Km + (size_t)b * Sq * Dm + h * DKh + (size_t)j0 * Dm;

#pragma unroll
    for (int c = t; c < 2048; c += 256) {
        int row = c >> 4, sg = c & 15;
        cp16(&Qs[row][sg*4], Qb + (size_t)row * Dm + sg*4);
    }
#pragma unroll
    for (int c = t; c < 2048; c += 256) {
        int row = c >> 4, sg = c & 15;
        cp16(&Ks[row][sg*4], Kb + (size_t)row * Dm + sg*4);
    }
    CP_COMMIT();
    CP_WAIT0();
    __syncthreads();

    const int wm = (wid & 3) * 32, wn = (wid >> 2) * 64;
    wmma::fragment<wmma::accumulator, 16, 16, 8, float> acc[2][4];
#pragma unroll
    for (int i = 0; i < 2; i++)
#pragma unroll
        for (int j = 0; j < 4; j++) wmma::fill_fragment(acc[i][j], 0.f);

#pragma unroll
    for (int ks = 0; ks < 64; ks += 8) {
        wmma::fragment<wmma::matrix_a, 16, 16, 8, wmma::precision::tf32,
                       wmma::row_major> af[2];
        wmma::fragment<wmma::matrix_b, 16, 16, 8, wmma::precision::tf32,
                       wmma::col_major> bf[4];
#pragma unroll
        for (int i = 0; i < 2; i++)
            wmma::load_matrix_sync(af[i], &Qs[wm + i*16][ks], 68);
#pragma unroll
        for (int j = 0; j < 4; j++)
            wmma::load_matrix_sync(bf[j], &Ks[wn + j*16][ks], 68);
#pragma unroll
        for (int i = 0; i < 2; i++)
#pragma unroll
            for (int j = 0; j < 4; j++)
                wmma::mma_sync(acc[i][j], af[i], bf[j], acc[i][j]);
    }
    __syncthreads();   // done with Qs/Ks; reuse as staging

#pragma unroll
    for (int i = 0; i < 2; i++)
#pragma unroll
        for (int j = 0; j < 4; j++)
            wmma::store_matrix_sync(&St[wm + i*16][wn + j*16], acc[i][j], 136,
                                    wmma::mem_row_major);
    __syncthreads();

    // epilogue: warp-per-row, fully coalesced 512B writes
    const int gjl = j0 + lane * 4;
#pragma unroll
    for (int r = 0; r < 16; r++) {
        const int row = wid * 16 + r;
        const int gi = i0 + row;
        float4 v = *(float4*)&St[row][lane * 4];
        v.x = (causal && gjl + 0 > gi) ? 0.f : __expf(v.x * 0.125f);
        v.y = (causal && gjl + 1 > gi) ? 0.f : __expf(v.y * 0.125f);
        v.z = (causal && gjl + 2 > gi) ? 0.f : __expf(v.z * 0.125f);
        v.w = (causal && gjl + 3 > gi) ? 0.f : __expf(v.w * 0.125f);
        float psum = v.x + v.y + v.z + v.w;
#pragma unroll
        for (int o = 16; o; o >>= 1)
            psum += __shfl_xor_sync(0xffffffffu, psum, o);
        *(float4*)&Ob[(size_t)gi * Sq + j0 + lane * 4] = v;
        if (lane == 0)
            part[((size_t)bh * Sq + gi) * 16 + jt] = psum;
    }
}

// ===== AV: MMA on raw E; writes aw = E/sum during load; scales out by 1/sum =
// 3-stage cp.async, one sync per iter; optional split-K via gridDim.z
__global__ void __launch_bounds__(256, 2) wm_av_norm(
    float* __restrict__ aw, const float* __restrict__ V,
    const float* __restrict__ part, float* __restrict__ outA,
    float* __restrict__ outB, int causal)
{
    extern __shared__ char sm[];
    float (*As)[128][24] = (float(*)[128][24])sm;            // 3 x 12288
    float (*Bs)[16][72]  = (float(*)[16][72])(sm + 36864);   // 3 x 4608
    float* invs          = (float*)(sm + 50688);             // 512
    float (*Os)[72]      = (float(*)[72])sm;                 // reuse: 36864

    const int bh = blockIdx.y;
    const int b = bh >> 3, h = bh & 7;
    const int i0 = blockIdx.x * 128;
    const int ks = blockIdx.z;
    const int t = threadIdx.x, wid = t >> 5, lane = t & 31;

    float* out = (ks == 0) ? outA : outB;
    float*       Abw = aw + (size_t)bh * Sq * Sq + (size_t)i0 * Sq;
    const float* Bb  = V + (size_t)b * Sq * Dm + h * DKh;
    float*       Cb  = out + (size_t)b * Sq * Dm + h * DKh;

    const int ktPer = 128 / gridDim.z;
    const int kt_lo = ks * ktPer;
    int kt_hi = kt_lo + ktPer;
    if (causal) { int ce = (i0 >> 4) + 8; if (ce < kt_hi) kt_hi = ce; }

    if (kt_hi <= kt_lo) {
        // no work: zero partial output region
        const float4 zero = make_float4(0.f, 0.f, 0.f, 0.f);
        for (int idx = t; idx < 2048; idx += 256) {
            int row = idx >> 4, c4 = idx & 15;
            *(float4*)&Cb[(size_t)(i0 + row) * Dm + c4 * 4] = zero;
        }
        return;
    }

    // per-row inverse softmax sums
    if (t < 128) {
        const float* pp = part + ((size_t)bh * Sq + i0 + t) * 16;
        float s = 0.f;
#pragma unroll
        for (int jt = 0; jt < 16; jt++) s += pp[jt];
        invs[t] = 1.f / s;
    }

    const int wm = (wid & 3) * 32, wn = (wid >> 2) * 32;
    wmma::fragment<wmma::accumulator, 16, 16, 8, float> acc[2][2];
#pragma unroll
    for (int i = 0; i < 2; i++)
#pragma unroll
        for (int j = 0; j < 2; j++) wmma::fill_fragment(acc[i][j], 0.f);

#define AV_LOAD(st, kt)                                                   \
    {                                                                     \
        _Pragma("unroll")                                                 \
        for (int c = t; c < 512; c += 256) {                              \
            int row = c >> 2, sg = c & 3;                                 \
            cp16(&As[st][row][sg*4],                                      \
                 Abw + (size_t)row * Sq + ((kt) << 4) + sg*4);            \
        }                                                                 \
        {                                                                 \
            int row = t >> 4, sg = t & 15;                                \
            cp16(&Bs[st][row][sg*4],                                      \
                 Bb + (size_t)(((kt) << 4) + row) * Dm + sg*4);           \
        }                                                                 \
        CP_COMMIT();                                                      \
    }

    AV_LOAD(0, kt_lo)
    if (kt_lo + 1 < kt_hi) AV_LOAD(1, kt_lo + 1)

    for (int kt = kt_lo; kt < kt_hi; kt++) {
        const int cur = (kt - kt_lo) % 3;
        if (kt + 1 < kt_hi) CP_WAIT1(); else CP_WAIT0();
        __syncthreads();
        if (kt + 2 < kt_hi) {
            int st = (kt - kt_lo + 2) % 3;
            AV_LOAD(st, kt + 2)
        }

        // write final normalized aw for this K-tile (reads raw E from smem)
        {
            int row = t >> 1, c0 = (t & 1) * 8;
            float inv = invs[row];
            float4 a0 = *(float4*)&As[cur][row][c0];
            float4 a1 = *(float4*)&As[cur][row][c0 + 4];
            a0.x *= inv; a0.y *= inv; a0.z *= inv; a0.w *= inv;
            a1.x *= inv; a1.y *= inv; a1.z *= inv; a1.w *= inv;
            float* aww = Abw + (size_t)row * Sq + (kt << 4) + c0;
            *(float4*)aww       = a0;
            *(float4*)(aww + 4) = a1;
        }

#pragma unroll
        for (int ksn = 0; ksn < 16; ksn += 8) {
            wmma::fragment<wmma::matrix_a, 16, 16, 8, wmma::precision::tf32,
                           wmma::row_major> af[2];
            wmma::fragment<wmma::matrix_b, 16, 16, 8, wmma::precision::tf32,
                           wmma::row_major> bf[2];
#pragma unroll
            for (int i = 0; i < 2; i++)
                wmma::load_matrix_sync(af[i], &As[cur][wm + i*16][ksn], 24);
#pragma unroll
            for (int j = 0; j < 2; j++)
                wmma::load_matrix_sync(bf[j], &Bs[cur][ksn][wn + j*16], 72);
#pragma unroll
            for (int i = 0; i < 2; i++)
#pragma unroll
                for (int j = 0; j < 2; j++)
                    wmma::mma_sync(acc[i][j], af[i], bf[j], acc[i][j]);
        }
    }
#undef AV_LOAD

    // epilogue: stage raw acc, then scale rows by 1/sum, coalesced write
    __syncthreads();
#pragma unroll
    for (int i = 0; i < 2; i++)
#pragma unroll
        for (int j = 0; j < 2; j++)
            wmma::store_matrix_sync(&Os[wm + i*16][wn + j*16], acc[i][j], 72,
                                    wmma::mem_row_major);
    __syncthreads();
#pragma unroll
    for (int r = 0; r < 16; r++) {
        const int row = wid * 16 + r;
        float2 v = *(float2*)&Os[row][lane * 2];
        const float inv = invs[row];
        v.x *= inv; v.y *= inv;
        *(float2*)&Cb[(size_t)(i0 + row) * Dm + lane * 2] = v;
    }
}

// ---------------- elementwise add (for split-K partials) --------------------
__global__ void __launch_bounds__(256) add2(
    float* __restrict__ a, const float* __restrict__ b)
{
    const size_t i = ((size_t)blockIdx.x * 256 + threadIdx.x) * 4;
    float4 va = *(float4*)&a[i];
    float4 vb = *(const float4*)&b[i];
    va.x += vb.x; va.y += vb.y; va.z += vb.z; va.w += vb.w;
    *(float4*)&a[i] = va;
}

// ---------------- residual add + layernorm over last dim (512) --------------
__global__ void __launch_bounds__(128) add_ln(
    const float* __restrict__ a, const float* __restrict__ r,
    const float* __restrict__ g, const float* __restrict__ be,
    float* __restrict__ out)
{
    const size_t row = blockIdx.x;
    const int t = threadIdx.x;
    __shared__ float red[4];

    float4 va = *(const float4*)&a[row * Dm + t*4];
    float4 vr = *(const float4*)&r[row * Dm + t*4];
    float x0 = va.x + vr.x, x1 = va.y + vr.y, x2 = va.z + vr.z, x3 = va.w + vr.w;

    float s = x0 + x1 + x2 + x3;
#pragma unroll
    for (int o = 16; o; o >>= 1) s += __shfl_xor_sync(0xffffffffu, s, o);
    if ((t & 31) == 0) red[t >> 5] = s;
    __syncthreads();
    float mean = (red[0] + red[1] + red[2] + red[3]) * (1.f / 512.f);

    float d0 = x0 - mean, d1 = x1 - mean, d2 = x2 - mean, d3 = x3 - mean;
    float vs = d0*d0 + d1*d1 + d2*d2 + d3*d3;
#pragma unroll
    for (int o = 16; o; o >>= 1) vs += __shfl_xor_sync(0xffffffffu, vs, o);
    __syncthreads();
    if ((t & 31) == 0) red[t >> 5] = vs;
    __syncthreads();
    float var = (red[0] + red[1] + red[2] + red[3]) * (1.f / 512.f);
    float rstd = rsqrtf(var + 1e-6f);

    float4 vg = *(const float4*)&g[t*4];
    float4 vb = *(const float4*)&be[t*4];
    float4 o4;
    o4.x = d0 * rstd * vg.x + vb.x;
    o4.y = d1 * rstd * vg.y + vb.y;
    o4.z = d2 * rstd * vg.z + vb.z;
    o4.w = d3 * rstd * vg.w + vb.w;
    *(float4*)&out[row * Dm + t*4] = o4;
}

// ---------------- launch ----------------------------------------------------
extern "C" void kernel_launch(void* const* d_in, const int* in_sizes, int n_in,
                              void* d_out, int out_size)
{
    const float* x    = (const float*)d_in[0];
    const float* enc  = (const float*)d_in[1];
    const float* wq1 = (const float*)d_in[3],  *bq1 = (const float*)d_in[4];
    const float* wk1 = (const float*)d_in[5],  *bk1 = (const float*)d_in[6];
    const float* wv1 = (const float*)d_in[7],  *bv1 = (const float*)d_in[8];
    const float* wo1 = (const float*)d_in[9],  *bo1 = (const float*)d_in[10];
    const float* wq2 = (const float*)d_in[11], *bq2 = (const float*)d_in[12];
    const float* wk2 = (const float*)d_in[13], *bk2 = (const float*)d_in[14];
    const float* wv2 = (const float*)d_in[15], *bv2 = (const float*)d_in[16];
    const float* wo2 = (const float*)d_in[17], *bo2 = (const float*)d_in[18];
    const float* wf1 = (const float*)d_in[19], *bf1 = (const float*)d_in[20];
    const float* wf2 = (const float*)d_in[21], *bf2 = (const float*)d_in[22];
    const float* g1 = (const float*)d_in[23], *be1 = (const float*)d_in[24];
    const float* g2 = (const float*)d_in[25], *be2 = (const float*)d_in[26];
    const float* g3 = (const float*)d_in[27], *be3 = (const float*)d_in[28];

    float* out3 = (float*)d_out;
    float* aw1  = out3 + (size_t)NB * Sq * Dm;
    float* aw2  = aw1  + (size_t)NB * NH * Sq * Sq;

    float *q, *k, *v, *t0, *t0b, *o1, *o2, *ffh, *part;
    cudaGetSymbolAddress((void**)&q,    g_q);
    cudaGetSymbolAddress((void**)&k,    g_k);
    cudaGetSymbolAddress((void**)&v,    g_v);
    cudaGetSymbolAddress((void**)&t0,   g_t0);
    cudaGetSymbolAddress((void**)&t0b,  g_t0b);
    cudaGetSymbolAddress((void**)&o1,   g_o1);
    cudaGetSymbolAddress((void**)&o2,   g_o2);
    cudaGetSymbolAddress((void**)&ffh,  g_ffh);
    cudaGetSymbolAddress((void**)&part, g_part);

    const int SMEM_GEMM  = 71680;
    const int SMEM_G64   = 53248;
    const int SMEM_LOG   = 69632;
    const int SMEM_AV    = 51200;
    cudaFuncSetAttribute(wm_gemm<false>, cudaFuncAttributeMaxDynamicSharedMemorySize, SMEM_GEMM);
    cudaFuncSetAttribute(wm_gemm<true>,  cudaFuncAttributeMaxDynamicSharedMemorySize, SMEM_GEMM);
    cudaFuncSetAttribute(wm_gemm3,       cudaFuncAttributeMaxDynamicSharedMemorySize, SMEM_GEMM);
    cudaFuncSetAttribute(wm_gemm64,      cudaFuncAttributeMaxDynamicSharedMemorySize, SMEM_G64);
    cudaFuncSetAttribute(wm_logits_exp,  cudaFuncAttributeMaxDynamicSharedMemorySize, SMEM_LOG);
    cudaFuncSetAttribute(wm_av_norm,     cudaFuncAttributeMaxDynamicSharedMemorySize, SMEM_AV);

    const dim3 gProj64(Dm / 128, MROWS / 64);       // (4, 64)
    const dim3 gQKV(12, MROWS / 128);               // (12, 32)
    const dim3 gFF1(FFd / 128, MROWS / 128);        // (16, 32)
    const dim3 gLog(Sq / 128, Sq / 128, NB * NH);   // (16, 16, 16)
    const dim3 gAV1(Sq / 128, NB * NH, 2);          // split-K causal
    const dim3 gAV2(Sq / 128, NB * NH, 1);
    const int  nAdd = (MROWS * Dm) / 4 / 256;       // 2048

    // ---- self attention ----
    wm_gemm3<<<gQKV, 256, SMEM_GEMM>>>(x, x, x, wq1, wk1, wv1,
                                       bq1, bk1, bv1, q, k, v, Dm, Dm);
    wm_logits_exp<<<gLog, 256, SMEM_LOG>>>(q, k, aw1, part, 1);
    wm_av_norm<<<gAV1, 256, SMEM_AV>>>(aw1, v, part, t0, t0b, 1);
    add2<<<nAdd, 256>>>(t0, t0b);
    wm_gemm64<<<gProj64, 256, SMEM_G64>>>(t0, wo1, bo1, q, Dm, Dm);
    add_ln<<<MROWS, 128>>>(q, x, g1, be1, o1);

    // ---- cross attention ----
    wm_gemm3<<<gQKV, 256, SMEM_GEMM>>>(o1, enc, enc, wq2, wk2, wv2,
                                       bq2, bk2, bv2, q, k, v, Dm, Dm);
    wm_logits_exp<<<gLog, 256, SMEM_LOG>>>(q, k, aw2, part, 0);
    wm_av_norm<<<gAV2, 256, SMEM_AV>>>(aw2, v, part, t0, t0b, 0);
    wm_gemm64<<<gProj64, 256, SMEM_G64>>>(t0, wo2, bo2, q, Dm, Dm);
    add_ln<<<MROWS, 128>>>(q, o1, g2, be2, o2);

    // ---- FFN ----
    wm_gemm<true ><<<gFF1, 256, SMEM_GEMM>>>(o2, wf1, bf1, ffh, FFd, Dm);
    wm_gemm64<<<gProj64, 256, SMEM_G64>>>(ffh, wf2, bf2, t0, Dm, FFd);
    add_ln<<<MROWS, 128>>>(t0, o2, g3, be3, out3);
}